// round 11
// baseline (speedup 1.0000x reference)
#include <cuda_runtime.h>
#include <cuda_fp16.h>
#include <math.h>

#define NN 10000
#define EE 100000
#define TP_NORM 0.125f       // 1/sqrt(C*S)
#define LOGIT_SCALE 0.125f   // DOT_NORM * SCALE
#define INV_RADIUS 0.2f

typedef unsigned long long u64;
typedef unsigned int u32;

// ---------------- scratch ----------------------------------------------------
// MMA-B layout: QB[n][p], p = k*128 + h*2 + s2; u32 word = (Q[h][2s2][k], Q[h][2s2+1][k]) halfs
__device__ u32  g_QBK[(size_t)NN * 2048];
__device__ u32  g_QBV[(size_t)NN * 2048];
__device__ u64  g_Qbkv[NN * 64];            // (K,V) f32 pairs: [n][s*16+k]
__device__ u64  g_WtK[32768];               // W2 re-layout: [c*2048 + p] = f32 pair over (s2 even, odd)
__device__ u64  g_WtV[32768];
__device__ u32  g_h1K[(size_t)EE * 32];     // half2 pairs (hid 2h,2h+1), ORIGINAL edge order
__device__ u32  g_h1V[(size_t)EE * 32];
__device__ float2 g_dc[EE];                 // (dst bitcast, cutoff)
__device__ float4 g_sh4[EE];                // sh
__device__ float g_qd[NN * 16];             // q @ W_dot
__device__ int   g_deg[NN];
__device__ int   g_rowptr[NN + 1];
__device__ int   g_cursor[NN];
__device__ int   g_eorder[EE];
__device__ float g_den[NN * 4];
__device__ float g_agg[NN * 16];

__device__ __forceinline__ float sigmoidf_(float x) { return 1.0f / (1.0f + expf(-x)); }
__device__ __forceinline__ u64 pk2(float lo, float hi) {
    u64 r; asm("mov.b64 %0, {%1, %2};" : "=l"(r) : "f"(lo), "f"(hi)); return r;
}
__device__ __forceinline__ float2 up2(u64 v) {
    float2 f; asm("mov.b64 {%0, %1}, %2;" : "=f"(f.x), "=f"(f.y) : "l"(v)); return f;
}
__device__ __forceinline__ u64 dup2(float x) { return pk2(x, x); }
__device__ __forceinline__ u64 fma2_(u64 a, u64 b, u64 c) {
    u64 d; asm("fma.rn.f32x2 %0, %1, %2, %3;" : "=l"(d) : "l"(a), "l"(b), "l"(c)); return d;
}
__device__ __forceinline__ u32 pack_h2(float lo, float hi) {
    __half2 h = __floats2half2_rn(lo, hi);
    return *reinterpret_cast<u32*>(&h);
}
__device__ __forceinline__ __half2 as_h2(u32 v) { return *reinterpret_cast<__half2*>(&v); }
__device__ __forceinline__ u32 h2_as_u32(__half2 h) { return *reinterpret_cast<u32*>(&h); }

// ================= PRO1: fused independent prologue (256-thread blocks) ======
#define PRO1_HIST   391
#define PRO1_TRANSW (PRO1_HIST + 256)
#define PRO1_QPROJD (PRO1_TRANSW + 625)
#define PRO1_TOTAL  (PRO1_QPROJD + 6250)

__global__ void __launch_bounds__(256) k_pro1(
    const int* __restrict__ eidx,
    const float* __restrict__ kW2, const float* __restrict__ vW2,
    const float* __restrict__ xf,  const float* __restrict__ Wq,
    const float* __restrict__ Wdot,
    const float* __restrict__ kb2, const float* __restrict__ vb2,
    const float* __restrict__ sh,  const float* __restrict__ emb,
    const float* __restrict__ elen,
    const float* __restrict__ kW1, const float* __restrict__ kb1,
    const float* __restrict__ vW1, const float* __restrict__ vb1) {

    int blk = blockIdx.x;
    int t = threadIdx.x;

    if (blk < PRO1_HIST) {
        int e = blk * 256 + t;
        if (e < EE) atomicAdd(&g_deg[eidx[e]], 1);

    } else if (blk < PRO1_TRANSW) {
        // ---- W2 re-layout for MMA-B production: Wt[c*2048 + p] = (W[h][c][2s2,k], W[h][c][2s2+1,k])
        int b = blk - PRO1_HIST;
        int tz = b >> 7;
        int i = (b & 127) * 256 + t;        // 0..32767
        const float* W = tz ? vW2 : kW2;
        u64* out = tz ? g_WtV : g_WtK;
        int c = i >> 11;
        int p = i & 2047;
        int k = p >> 7;
        int h = (p >> 1) & 63;
        int s2 = p & 1;
        const float* Wh = W + h * 1024 + c * 64 + s2 * 32 + k;
        out[c * 2048 + p] = pk2(Wh[0], Wh[16]);

    } else if (blk < PRO1_QPROJD) {
        __shared__ float Wqs[256], Wds[16], Xs[16][16], B2K[1024], B2V[1024];
        if (t < 256) Wqs[t] = Wq[t];
        if (t < 16)  Wds[t] = Wdot[t];
        for (int i = t; i < 1024; i += 256) { B2K[i] = kb2[i]; B2V[i] = vb2[i]; }
        int n0 = (blk - PRO1_TRANSW) * 16;
        { int nl = t >> 4, c = t & 15; Xs[nl][c] = xf[(n0 + nl) * 16 + c]; }
        __syncthreads();
        int nl = t >> 4, k = t & 15;
        int n = n0 + nl;
        int head = k >> 2, j = k & 3;
        float qd = 0.0f;
#pragma unroll
        for (int i2 = 0; i2 < 4; i2++) {
            float q = 0.0f;
#pragma unroll
            for (int c = 0; c < 16; c++) q += Xs[nl][c] * Wqs[c * 16 + head * 4 + i2];
            qd += q * Wds[i2 * 4 + j];
        }
        g_qd[n * 16 + k] = qd;
#pragma unroll
        for (int s = 0; s < 4; s++) {
            float aK = 0.0f, aV = 0.0f;
#pragma unroll
            for (int c = 0; c < 16; c++) {
                float x = Xs[nl][c];
                aK += x * B2K[c * 64 + s * 16 + k];
                aV += x * B2V[c * 64 + s * 16 + k];
            }
            g_Qbkv[n * 64 + s * 16 + k] = pk2(aK, aV);
        }

    } else {
        __shared__ float emb_s[16][16];
        int e0 = (blk - PRO1_QPROJD) * 16;
        { int el = t >> 4, b = t & 15; emb_s[el][b] = emb[(e0 + el) * 16 + b]; }
        if (t < 16) {
            int e = e0 + t;
            int ds = eidx[EE + e];
            float cut = sigmoidf_(10.0f * (1.0f - elen[e] * INV_RADIUS));
            g_dc[e] = make_float2(__int_as_float(ds), cut);
            g_sh4[e] = *reinterpret_cast<const float4*>(sh + e * 4);
        }
        __syncthreads();
        int h = t & 31, tz = (t >> 5) & 1, elg = t >> 6;
        const u64* __restrict__ W1 = reinterpret_cast<const u64*>(tz ? vW1 : kW1);
        const u64* __restrict__ b1 = reinterpret_cast<const u64*>(tz ? vb1 : kb1);
        u32* __restrict__ H = tz ? g_h1V : g_h1K;
        u64 w1r[16];
#pragma unroll
        for (int b = 0; b < 16; b++) w1r[b] = __ldg(&W1[b * 32 + h]);
        u64 bb = __ldg(&b1[h]);
#pragma unroll
        for (int r = 0; r < 4; r++) {
            int el = r * 4 + elg;
            u64 acc = bb;
#pragma unroll
            for (int b = 0; b < 16; b++) acc = fma2_(dup2(emb_s[el][b]), w1r[b], acc);
            float2 f = up2(acc);
            f.x = f.x * sigmoidf_(f.x);
            f.y = f.y * sigmoidf_(f.y);
            H[(size_t)(e0 + el) * 32 + h] = pack_h2(f.x, f.y);
        }
    }
}

// ================= PRO2: scan (block 0) + qweights (blocks 1..1256) ==========
__global__ void __launch_bounds__(512) k_pro2(const float* __restrict__ xf) {
    int blk = blockIdx.x;
    int t = threadIdx.x;

    if (blk == 0) {
        __shared__ int ps[512];
        const int PER = 20;
        int start = t * PER;
        int sum = 0;
        int local[PER];
        for (int i = 0; i < PER; i++) {
            int idx = start + i;
            local[i] = (idx < NN) ? g_deg[idx] : 0;
            if (idx < NN) g_deg[idx] = 0;
            sum += local[i];
        }
        ps[t] = sum;
        __syncthreads();
        for (int off = 1; off < 512; off <<= 1) {
            int add = (t >= off) ? ps[t - off] : 0;
            __syncthreads();
            ps[t] += add;
            __syncthreads();
        }
        int base = ps[t] - sum;
        for (int i = 0; i < PER; i++) {
            int idx = start + i;
            if (idx < NN) { g_rowptr[idx] = base; g_cursor[idx] = base; base += local[i]; }
        }
        if (t == 511) g_rowptr[NN] = ps[511];

    } else {
        // ---- Q tensors directly in MMA-B layout (fp16 out, W register-cached)
        int b = blk - 1;                    // 0..1255
        int n0 = (b % 157) * 64;
        int y = (b / 157) & 3;              // p-slice
        int tz = b / 628;
        __shared__ u64 Xd[64 * 16];
        for (int i = t; i < 1024; i += 512) {
            int n = n0 + (i >> 4);
            Xd[i] = dup2((n < NN) ? xf[n * 16 + (i & 15)] : 0.0f);
        }
        __syncthreads();
        int p = y * 512 + t;                // 0..2047
        const u64* __restrict__ Wt = tz ? g_WtV : g_WtK;
        u32* __restrict__ QB = tz ? g_QBV : g_QBK;
        u64 wreg[16];
#pragma unroll
        for (int c = 0; c < 16; c++) wreg[c] = __ldg(&Wt[c * 2048 + p]);
#pragma unroll 4
        for (int n = 0; n < 64; n++) {
            u64 acc = 0ULL;
#pragma unroll
            for (int c = 0; c < 16; c++) acc = fma2_(Xd[n * 16 + c], wreg[c], acc);
            if (n0 + n < NN) {
                float2 f = up2(acc);
                QB[(size_t)(n0 + n) * 2048 + p] = pack_h2(f.x, f.y);
            }
        }
    }
}

// ---------------- scatter edges grouped by src --------------------------------
__global__ void k_scatter(const int* __restrict__ eidx) {
    int e = blockIdx.x * 256 + threadIdx.x;
    if (e < EE) {
        int s = eidx[e];
        int pos = atomicAdd(&g_cursor[s], 1);
        g_eorder[pos] = e;
    }
}

// ---------------- main edge contraction: tensor-core MMA per node tile --------
// OUT[es,k] = A(16x256) @ B(256x16), A[es][h*4+s] = h1[es][h]*sh[es][s], B = Q.
// 8 warps x 2 k-chunks each; f32 accum; partials reduced in smem.
__global__ void __launch_bounds__(256, 4) k_edges() {
    __shared__ u32   QBs[2 * 2112];          // [T][n(16) x 132-padded]
    __shared__ float Cs[8][2][16][16];       // per-warp C partials
    __shared__ u32   h1Ks[16][32];
    __shared__ u32   h1Vs[16][32];
    __shared__ u64   Qbs[64];
    __shared__ float4 shS[16];
    __shared__ u32   shp[16][2];             // half2 sh pairs (s0,s1),(s2,s3)
    __shared__ int   dstS[16];
    __shared__ float cutS[16];
    __shared__ float2 kvs[16][16];

    int node = blockIdx.x;
    int t = threadIdx.x;

    int r0 = g_rowptr[node], deg = g_rowptr[node + 1] - r0;
    if (deg == 0) return;

    // stage Q (both tensors) into bank-padded smem, coalesced
    for (int i = t; i < 4096; i += 256) {
        int T = i >> 11;
        int p = i & 2047;
        u32 v = T ? __ldg(&g_QBV[(size_t)node * 2048 + p])
                  : __ldg(&g_QBK[(size_t)node * 2048 + p]);
        QBs[T * 2112 + (p >> 7) * 132 + (p & 127)] = v;
    }
    if (t < 64) Qbs[t] = g_Qbkv[node * 64 + t];

    int lane = t & 31, w = t >> 5;
    int gq = lane >> 2, tid = lane & 3;
    u32 prmtc = ((tid >> 1) & 1) ? 0x3232u : 0x1010u;   // dup hi/lo half

    for (int base = 0; base < deg; base += 16) {
        int nval = min(16, deg - base);
        // ---- staging: h1 tiles (zero-padded!) + per-edge meta ----
        {
            int esw = t >> 5, h = t & 31;
#pragma unroll
            for (int r = 0; r < 2; r++) {
                int es = r * 8 + esw;
                if (es < nval) {
                    int e = __ldg(&g_eorder[r0 + base + es]);
                    h1Ks[es][h] = __ldg(&g_h1K[(size_t)e * 32 + h]);
                    h1Vs[es][h] = __ldg(&g_h1V[(size_t)e * 32 + h]);
                } else {
                    h1Ks[es][h] = 0u;
                    h1Vs[es][h] = 0u;
                }
            }
            if (t < 16) {
                if (t < nval) {
                    int e2 = __ldg(&g_eorder[r0 + base + t]);
                    float2 dc = g_dc[e2];
                    dstS[t] = __float_as_int(dc.x);
                    cutS[t] = dc.y;
                    float4 s4 = g_sh4[e2];
                    shS[t] = s4;
                    shp[t][0] = h2_as_u32(__floats2half2_rn(s4.x, s4.y));
                    shp[t][1] = h2_as_u32(__floats2half2_rn(s4.z, s4.w));
                } else {
                    dstS[t] = -1;
                    shS[t] = make_float4(0.f, 0.f, 0.f, 0.f);
                    shp[t][0] = 0u; shp[t][1] = 0u;
                }
            }
        }
        __syncthreads();

        // ---- MMA: warp w covers hs-chunks 2w, 2w+1 (16 each) ----
#pragma unroll
        for (int T = 0; T < 2; T++) {
            const u32 (*h1s)[32] = T ? h1Vs : h1Ks;
            float c0[4] = {0.f, 0.f, 0.f, 0.f};
            float c1[4] = {0.f, 0.f, 0.f, 0.f};
#pragma unroll
            for (int kk2 = 0; kk2 < 2; kk2++) {
                int kc = w * 2 + kk2;
                u32 wa = h1s[gq][kc * 2],     wb = h1s[gq + 8][kc * 2];
                u32 wc = h1s[gq][kc * 2 + 1], wd = h1s[gq + 8][kc * 2 + 1];
                u32 sp0 = shp[gq][tid & 1],   sp1 = shp[gq + 8][tid & 1];
                u32 a0 = h2_as_u32(__hmul2(as_h2(__byte_perm(wa, wa, prmtc)), as_h2(sp0)));
                u32 a1 = h2_as_u32(__hmul2(as_h2(__byte_perm(wb, wb, prmtc)), as_h2(sp1)));
                u32 a2 = h2_as_u32(__hmul2(as_h2(__byte_perm(wc, wc, prmtc)), as_h2(sp0)));
                u32 a3 = h2_as_u32(__hmul2(as_h2(__byte_perm(wd, wd, prmtc)), as_h2(sp1)));
                int qb0 = T * 2112 + gq * 132 + kc * 8 + tid;
                {
                    u32 b0 = QBs[qb0];
                    u32 b1 = QBs[qb0 + 4];
                    asm volatile(
                        "mma.sync.aligned.m16n8k16.row.col.f32.f16.f16.f32 "
                        "{%0,%1,%2,%3}, {%4,%5,%6,%7}, {%8,%9}, {%0,%1,%2,%3};"
                        : "+f"(c0[0]), "+f"(c0[1]), "+f"(c0[2]), "+f"(c0[3])
                        : "r"(a0), "r"(a1), "r"(a2), "r"(a3), "r"(b0), "r"(b1));
                }
                {
                    u32 b0 = QBs[qb0 + 8 * 132];
                    u32 b1 = QBs[qb0 + 8 * 132 + 4];
                    asm volatile(
                        "mma.sync.aligned.m16n8k16.row.col.f32.f16.f16.f32 "
                        "{%0,%1,%2,%3}, {%4,%5,%6,%7}, {%8,%9}, {%0,%1,%2,%3};"
                        : "+f"(c1[0]), "+f"(c1[1]), "+f"(c1[2]), "+f"(c1[3])
                        : "r"(a0), "r"(a1), "r"(a2), "r"(a3), "r"(b0), "r"(b1));
                }
            }
            Cs[w][T][gq][tid * 2]         = c0[0];
            Cs[w][T][gq][tid * 2 + 1]     = c0[1];
            Cs[w][T][gq + 8][tid * 2]     = c0[2];
            Cs[w][T][gq + 8][tid * 2 + 1] = c0[3];
            Cs[w][T][gq][8 + tid * 2]         = c1[0];
            Cs[w][T][gq][8 + tid * 2 + 1]     = c1[1];
            Cs[w][T][gq + 8][8 + tid * 2]     = c1[2];
            Cs[w][T][gq + 8][8 + tid * 2 + 1] = c1[3];
        }
        __syncthreads();

        // ---- reduce 8 warp-partials + bias + TP_NORM ----
        {
            int es = t >> 4, k = t & 15;
            float sK = 0.f, sV = 0.f;
#pragma unroll
            for (int ww = 0; ww < 8; ww++) {
                sK += Cs[ww][0][es][k];
                sV += Cs[ww][1][es][k];
            }
            float4 s4 = shS[es];
            u64 bacc = fma2_(dup2(s4.x), Qbs[k], 0ULL);
            bacc = fma2_(dup2(s4.y), Qbs[16 + k], bacc);
            bacc = fma2_(dup2(s4.z), Qbs[32 + k], bacc);
            bacc = fma2_(dup2(s4.w), Qbs[48 + k], bacc);
            float2 bb = up2(bacc);
            kvs[es][k] = make_float2((sK + bb.x) * TP_NORM, (sV + bb.y) * TP_NORM);
        }
        __syncthreads();

        // ---- epilogue: logits + softmax-numerator atomics ----
        {
            int es = t >> 4, kk = t & 15, hd = kk >> 2;
            int ds = dstS[es];
            if (ds >= 0) {
                float4 qd = *reinterpret_cast<const float4*>(g_qd + ds * 16 + hd * 4);
                const float2* kr = &kvs[es][hd * 4];
                float lg = kr[0].x * qd.x + kr[1].x * qd.y + kr[2].x * qd.z + kr[3].x * qd.w;
                float ex = expf(lg * LOGIT_SCALE * cutS[es]);
                if ((kk & 3) == 0) atomicAdd(&g_den[ds * 4 + hd], ex);
                atomicAdd(&g_agg[ds * 16 + kk], ex * kvs[es][kk].y);
            }
        }
        __syncthreads();
    }
}

// ---------------- finalize per node (W_out, skip, FFN) + re-zero --------------
__global__ void k_final(const float* __restrict__ xf,
                        const float* __restrict__ Wout,
                        const float* __restrict__ Wf1,
                        const float* __restrict__ Wf2,
                        float* __restrict__ out) {
    __shared__ float Wo[256], F1[512], F2[512];
    int t = threadIdx.x;
    if (t < 256) Wo[t] = Wout[t];
    for (int i = t; i < 512; i += 256) { F1[i] = Wf1[i]; F2[i] = Wf2[i]; }
    __syncthreads();
    int n = blockIdx.x * 256 + t;
    if (n >= NN) return;

    float a[16];
#pragma unroll
    for (int k = 0; k < 16; k++) {
        float d = g_den[n * 4 + (k >> 2)];
        a[k] = (d > 0.0f) ? g_agg[n * 16 + k] / d : 0.0f;
        g_agg[n * 16 + k] = 0.0f;            // re-zero for next replay
    }
#pragma unroll
    for (int h = 0; h < 4; h++) g_den[n * 4 + h] = 0.0f;
    float attn[16];
#pragma unroll
    for (int k = 0; k < 16; k++) {
        float s = xf[n * 16 + k];
#pragma unroll
        for (int jj = 0; jj < 16; jj++) s += a[jj] * Wo[jj * 16 + k];
        attn[k] = s;
    }
    float na[32];
#pragma unroll
    for (int jj = 0; jj < 32; jj++) {
        float f = 0.0f;
#pragma unroll
        for (int i = 0; i < 16; i++) f += attn[i] * F1[i * 32 + jj];
        na[jj] = f * sigmoidf_(fabsf(f));
    }
#pragma unroll
    for (int k = 0; k < 16; k++) {
        float o = attn[k];
#pragma unroll
        for (int jj = 0; jj < 32; jj++) o += na[jj] * F2[jj * 16 + k];
        out[n * 16 + k] = o;
    }
}

// ---------------- launch ------------------------------------------------------
extern "C" void kernel_launch(void* const* d_in, const int* in_sizes, int n_in,
                              void* d_out, int out_size) {
    const float* xf   = (const float*)d_in[0];
    const float* sh   = (const float*)d_in[1];
    const float* emb  = (const float*)d_in[2];
    const float* elen = (const float*)d_in[3];
    const float* Wq   = (const float*)d_in[4];
    const float* kW1  = (const float*)d_in[5];
    const float* kb1  = (const float*)d_in[6];
    const float* kW2  = (const float*)d_in[7];
    const float* kb2  = (const float*)d_in[8];
    const float* vW1  = (const float*)d_in[9];
    const float* vb1  = (const float*)d_in[10];
    const float* vW2  = (const float*)d_in[11];
    const float* vb2  = (const float*)d_in[12];
    const float* Wdot = (const float*)d_in[13];
    const float* Wout = (const float*)d_in[14];
    const float* Wf1  = (const float*)d_in[15];
    const float* Wf2  = (const float*)d_in[16];
    const int*   eidx = (const int*)d_in[17];
    float* out = (float*)d_out;

    k_pro1<<<PRO1_TOTAL, 256>>>(eidx, kW2, vW2, xf, Wq, Wdot, kb2, vb2,
                                sh, emb, elen, kW1, kb1, vW1, vb1);
    k_pro2<<<1257, 512>>>(xf);
    k_scatter<<<(EE + 255) / 256, 256>>>(eidx);
    k_edges<<<NN, 256>>>();
    k_final<<<(NN + 255) / 256, 256>>>(xf, Wout, Wf1, Wf2, out);
}

// round 12
// speedup vs baseline: 1.2569x; 1.2569x over previous
#include <cuda_runtime.h>
#include <cuda_fp16.h>
#include <math.h>

#define NN 10000
#define EE 100000
#define TP_NORM 0.125f       // 1/sqrt(C*S)
#define LOGIT_SCALE 0.125f   // DOT_NORM * SCALE
#define INV_RADIUS 0.2f

typedef unsigned long long u64;
typedef unsigned int u32;

// ---------------- scratch ----------------------------------------------------
__device__ u32  g_QhK[(size_t)NN * 2048];   // half2 pairs (hid 2h,2h+1): [n][(s*16+k)*32 + h]
__device__ u32  g_QhV[(size_t)NN * 2048];
__device__ u64  g_Qbkv[NN * 64];            // (K,V) f32 pairs: [n][s*16+k]
__device__ u64  g_WtK[32768];               // W2 transposed: [(c*64+sk)*32 + h]
__device__ u64  g_WtV[32768];
__device__ u32  g_h1K[(size_t)EE * 32];     // half2 pairs, ORIGINAL edge order
__device__ u32  g_h1V[(size_t)EE * 32];
__device__ float2 g_dc[EE];                 // (dst bitcast, cutoff), original order
__device__ float4 g_sh4[EE];                // sh, original order
__device__ float g_qd[NN * 16];             // q @ W_dot
__device__ int   g_deg[NN];
__device__ int   g_rowptr[NN + 1];
__device__ int   g_cursor[NN];
__device__ int   g_eorder[EE];
__device__ float g_den[NN * 4];
__device__ float g_agg[NN * 16];

__device__ __forceinline__ float sigmoidf_(float x) { return 1.0f / (1.0f + expf(-x)); }
__device__ __forceinline__ u64 pk2(float lo, float hi) {
    u64 r; asm("mov.b64 %0, {%1, %2};" : "=l"(r) : "f"(lo), "f"(hi)); return r;
}
__device__ __forceinline__ float2 up2(u64 v) {
    float2 f; asm("mov.b64 {%0, %1}, %2;" : "=f"(f.x), "=f"(f.y) : "l"(v)); return f;
}
__device__ __forceinline__ u64 dup2(float x) { return pk2(x, x); }
__device__ __forceinline__ u64 fma2_(u64 a, u64 b, u64 c) {
    u64 d; asm("fma.rn.f32x2 %0, %1, %2, %3;" : "=l"(d) : "l"(a), "l"(b), "l"(c)); return d;
}
__device__ __forceinline__ u32 pack_h2(float lo, float hi) {
    __half2 h = __floats2half2_rn(lo, hi);
    return *reinterpret_cast<u32*>(&h);
}
__device__ __forceinline__ __half2 as_h2(u32 v) { return *reinterpret_cast<__half2*>(&v); }
__device__ __forceinline__ u32 h2_as_u32(__half2 h) { return *reinterpret_cast<u32*>(&h); }

// ================= PRO1: fused independent prologue (256-thread blocks) ======
// block ranges: [0,391) hist | [391,647) transW | [647,1272) qprojd | [1272,7522) mlp
#define PRO1_HIST   391
#define PRO1_TRANSW (PRO1_HIST + 256)
#define PRO1_QPROJD (PRO1_TRANSW + 625)
#define PRO1_TOTAL  (PRO1_QPROJD + 6250)

__global__ void __launch_bounds__(256) k_pro1(
    const int* __restrict__ eidx,
    const float* __restrict__ kW2, const float* __restrict__ vW2,
    const float* __restrict__ xf,  const float* __restrict__ Wq,
    const float* __restrict__ Wdot,
    const float* __restrict__ kb2, const float* __restrict__ vb2,
    const float* __restrict__ sh,  const float* __restrict__ emb,
    const float* __restrict__ elen,
    const float* __restrict__ kW1, const float* __restrict__ kb1,
    const float* __restrict__ vW1, const float* __restrict__ vb1) {

    int blk = blockIdx.x;
    int t = threadIdx.x;

    if (blk < PRO1_HIST) {
        int e = blk * 256 + t;
        if (e < EE) atomicAdd(&g_deg[eidx[e]], 1);

    } else if (blk < PRO1_TRANSW) {
        int b = blk - PRO1_HIST;
        int tz = b >> 7;
        int i = (b & 127) * 256 + t;
        const float* W = tz ? vW2 : kW2;
        u64* out = tz ? g_WtV : g_WtK;
        int h = i & 31, csk = i >> 5;
        out[i] = pk2(W[(2 * h) * 1024 + csk], W[(2 * h + 1) * 1024 + csk]);

    } else if (blk < PRO1_QPROJD) {
        __shared__ float Wqs[256], Wds[16], Xs[16][16], B2K[1024], B2V[1024];
        if (t < 256) Wqs[t] = Wq[t];
        if (t < 16)  Wds[t] = Wdot[t];
        for (int i = t; i < 1024; i += 256) { B2K[i] = kb2[i]; B2V[i] = vb2[i]; }
        int n0 = (blk - PRO1_TRANSW) * 16;
        { int nl = t >> 4, c = t & 15; Xs[nl][c] = xf[(n0 + nl) * 16 + c]; }
        __syncthreads();
        int nl = t >> 4, k = t & 15;
        int n = n0 + nl;
        int head = k >> 2, j = k & 3;
        float qd = 0.0f;
#pragma unroll
        for (int i2 = 0; i2 < 4; i2++) {
            float q = 0.0f;
#pragma unroll
            for (int c = 0; c < 16; c++) q += Xs[nl][c] * Wqs[c * 16 + head * 4 + i2];
            qd += q * Wds[i2 * 4 + j];
        }
        g_qd[n * 16 + k] = qd;
#pragma unroll
        for (int s = 0; s < 4; s++) {
            float aK = 0.0f, aV = 0.0f;
#pragma unroll
            for (int c = 0; c < 16; c++) {
                float x = Xs[nl][c];
                aK += x * B2K[c * 64 + s * 16 + k];
                aV += x * B2V[c * 64 + s * 16 + k];
            }
            g_Qbkv[n * 64 + s * 16 + k] = pk2(aK, aV);
        }

    } else {
        __shared__ float emb_s[16][16];
        int e0 = (blk - PRO1_QPROJD) * 16;
        { int el = t >> 4, b = t & 15; emb_s[el][b] = emb[(e0 + el) * 16 + b]; }
        if (t < 16) {
            int e = e0 + t;
            int ds = eidx[EE + e];
            float cut = sigmoidf_(10.0f * (1.0f - elen[e] * INV_RADIUS));
            g_dc[e] = make_float2(__int_as_float(ds), cut);
            g_sh4[e] = *reinterpret_cast<const float4*>(sh + e * 4);
        }
        __syncthreads();
        int h = t & 31, tz = (t >> 5) & 1, elg = t >> 6;
        const u64* __restrict__ W1 = reinterpret_cast<const u64*>(tz ? vW1 : kW1);
        const u64* __restrict__ b1 = reinterpret_cast<const u64*>(tz ? vb1 : kb1);
        u32* __restrict__ H = tz ? g_h1V : g_h1K;
        u64 w1r[16];
#pragma unroll
        for (int b = 0; b < 16; b++) w1r[b] = __ldg(&W1[b * 32 + h]);
        u64 bb = __ldg(&b1[h]);
#pragma unroll
        for (int r = 0; r < 4; r++) {
            int el = r * 4 + elg;
            u64 acc = bb;
#pragma unroll
            for (int b = 0; b < 16; b++) acc = fma2_(dup2(emb_s[el][b]), w1r[b], acc);
            float2 f = up2(acc);
            f.x = f.x * sigmoidf_(f.x);
            f.y = f.y * sigmoidf_(f.y);
            H[(size_t)(e0 + el) * 32 + h] = pack_h2(f.x, f.y);
        }
    }
}

// ================= PRO2: scan (block 0) + qweights (blocks 1..1256) ==========
__global__ void __launch_bounds__(512) k_pro2(const float* __restrict__ xf) {
    int blk = blockIdx.x;
    int t = threadIdx.x;

    if (blk == 0) {
        __shared__ int ps[512];
        const int PER = 20;
        int start = t * PER;
        int sum = 0;
        int local[PER];
        for (int i = 0; i < PER; i++) {
            int idx = start + i;
            local[i] = (idx < NN) ? g_deg[idx] : 0;
            if (idx < NN) g_deg[idx] = 0;
            sum += local[i];
        }
        ps[t] = sum;
        __syncthreads();
        for (int off = 1; off < 512; off <<= 1) {
            int add = (t >= off) ? ps[t - off] : 0;
            __syncthreads();
            ps[t] += add;
            __syncthreads();
        }
        int base = ps[t] - sum;
        for (int i = 0; i < PER; i++) {
            int idx = start + i;
            if (idx < NN) { g_rowptr[idx] = base; g_cursor[idx] = base; base += local[i]; }
        }
        if (t == 511) g_rowptr[NN] = ps[511];

    } else {
        int b = blk - 1;
        int n0 = (b % 157) * 64;
        int h8 = ((b / 157) & 3) * 8;
        int tz = b / 628;
        __shared__ u64 Xd[64 * 16];
        for (int i = t; i < 1024; i += 512) {
            int n = n0 + (i >> 4);
            Xd[i] = dup2((n < NN) ? xf[n * 16 + (i & 15)] : 0.0f);
        }
        __syncthreads();
        int hp = t & 7, sk = t >> 3;
        const u64* __restrict__ Wt = tz ? g_WtV : g_WtK;
        u32* __restrict__ Qh = tz ? g_QhV : g_QhK;
        u64 wreg[16];
#pragma unroll
        for (int c = 0; c < 16; c++) wreg[c] = __ldg(&Wt[(c * 64 + sk) * 32 + h8 + hp]);
#pragma unroll 4
        for (int n = 0; n < 64; n++) {
            u64 acc = 0ULL;
#pragma unroll
            for (int c = 0; c < 16; c++) acc = fma2_(Xd[n * 16 + c], wreg[c], acc);
            if (n0 + n < NN) {
                float2 f = up2(acc);
                Qh[(size_t)(n0 + n) * 2048 + sk * 32 + h8 + hp] = pack_h2(f.x, f.y);
            }
        }
    }
}

// ---------------- scatter edges grouped by src --------------------------------
__global__ void k_scatter(const int* __restrict__ eidx) {
    int e = blockIdx.x * 256 + threadIdx.x;
    if (e < EE) {
        int s = eidx[e];
        int pos = atomicAdd(&g_cursor[s], 1);
        g_eorder[pos] = e;
    }
}

// ---------------- main edge contraction (one block per source node) -----------
// 256 threads: k = t>>4 (channel), g = t&15 (hid-pair slice, pair h = i*16+g).
// Q raw half2 regs; dd AND the 2-term hid-accumulate in HFMA2; f32 shfl reduce.
__global__ void __launch_bounds__(256, 4) k_edges() {
    __shared__ int    dstS[16];
    __shared__ float  cutS[16];
    __shared__ float4 shS[16];
    __shared__ u32    sh2S[16][4];      // duplicated-half2 sh per edge slot
    __shared__ u32    h1Ks[16][32];
    __shared__ u32    h1Vs[16][32];
    __shared__ float2 kvs[16][16];

    int node = blockIdx.x;
    int t = threadIdx.x;
    int k = t >> 4, g = t & 15;

    // per-node Q slice, kept packed as half2 (16+16 u32 registers)
    const u32* __restrict__ QK = g_QhK + (size_t)node * 2048;
    const u32* __restrict__ QV = g_QhV + (size_t)node * 2048;
    u32 qK[2][4], qV[2][4];
#pragma unroll
    for (int i = 0; i < 2; i++)
#pragma unroll
        for (int s = 0; s < 4; s++) {
            int idx = (s * 16 + k) * 32 + i * 16 + g;
            qK[i][s] = __ldg(&QK[idx]);
            qV[i][s] = __ldg(&QV[idx]);
        }

    int r0 = g_rowptr[node], deg = g_rowptr[node + 1] - r0;
    if (deg == 0) return;

    u64 qb[4];
    if (g == 0) {
#pragma unroll
        for (int s = 0; s < 4; s++) qb[s] = g_Qbkv[node * 64 + s * 16 + k];
    }

    for (int base = 0; base < deg; base += 16) {
        int nval = min(16, deg - base);
        // ---- staging: h1 tiles (2 rounds of 8 es) + per-edge meta ----
        {
            int esw = t >> 5, h = t & 31;
#pragma unroll
            for (int r = 0; r < 2; r++) {
                int es = r * 8 + esw;
                if (es < nval) {
                    int e = __ldg(&g_eorder[r0 + base + es]);
                    h1Ks[es][h] = __ldg(&g_h1K[(size_t)e * 32 + h]);
                    h1Vs[es][h] = __ldg(&g_h1V[(size_t)e * 32 + h]);
                }
            }
            if (t < 16) {
                if (t < nval) {
                    int e2 = __ldg(&g_eorder[r0 + base + t]);
                    float2 dc = g_dc[e2];
                    dstS[t] = __float_as_int(dc.x);
                    cutS[t] = dc.y;
                    float4 s4 = g_sh4[e2];
                    shS[t] = s4;
                    sh2S[t][0] = h2_as_u32(__float2half2_rn(s4.x));
                    sh2S[t][1] = h2_as_u32(__float2half2_rn(s4.y));
                    sh2S[t][2] = h2_as_u32(__float2half2_rn(s4.z));
                    sh2S[t][3] = h2_as_u32(__float2half2_rn(s4.w));
                } else {
                    dstS[t] = -1;
                }
            }
        }
        __syncthreads();

        // ---- compute: runtime-bounded loop over live edge slots ----
#pragma unroll 4
        for (int es = 0; es < nval; es++) {
            __half2 s0 = as_h2(sh2S[es][0]);
            __half2 s1 = as_h2(sh2S[es][1]);
            __half2 s2 = as_h2(sh2S[es][2]);
            __half2 s3 = as_h2(sh2S[es][3]);
            __half2 accK = __half2half2(__ushort_as_half(0));
            __half2 accV = accK;
#pragma unroll
            for (int i = 0; i < 2; i++) {
                __half2 dK = __hmul2(s0, as_h2(qK[i][0]));
                dK = __hfma2(s1, as_h2(qK[i][1]), dK);
                dK = __hfma2(s2, as_h2(qK[i][2]), dK);
                dK = __hfma2(s3, as_h2(qK[i][3]), dK);
                __half2 dV = __hmul2(s0, as_h2(qV[i][0]));
                dV = __hfma2(s1, as_h2(qV[i][1]), dV);
                dV = __hfma2(s2, as_h2(qV[i][2]), dV);
                dV = __hfma2(s3, as_h2(qV[i][3]), dV);
                accK = __hfma2(as_h2(h1Ks[es][i * 16 + g]), dK, accK);
                accV = __hfma2(as_h2(h1Vs[es][i * 16 + g]), dV, accV);
            }
            float2 fK = __half22float2(accK);
            float2 fV = __half22float2(accV);
            float kv_k = fK.x + fK.y;
            float kv_v = fV.x + fV.y;
            kv_k += __shfl_xor_sync(0xffffffffu, kv_k, 1);
            kv_v += __shfl_xor_sync(0xffffffffu, kv_v, 1);
            kv_k += __shfl_xor_sync(0xffffffffu, kv_k, 2);
            kv_v += __shfl_xor_sync(0xffffffffu, kv_v, 2);
            kv_k += __shfl_xor_sync(0xffffffffu, kv_k, 4);
            kv_v += __shfl_xor_sync(0xffffffffu, kv_v, 4);
            kv_k += __shfl_xor_sync(0xffffffffu, kv_k, 8);
            kv_v += __shfl_xor_sync(0xffffffffu, kv_v, 8);
            if (g == 0) {
                float4 s4 = shS[es];
                u64 bacc = fma2_(dup2(s4.x), qb[0], 0ULL);
                bacc = fma2_(dup2(s4.y), qb[1], bacc);
                bacc = fma2_(dup2(s4.z), qb[2], bacc);
                bacc = fma2_(dup2(s4.w), qb[3], bacc);
                float2 bb = up2(bacc);
                kvs[es][k] = make_float2((kv_k + bb.x) * TP_NORM, (kv_v + bb.y) * TP_NORM);
            }
        }
        __syncthreads();

        // ---- epilogue: all 256 threads, one atomic each (16 es x 16 kk) ----
        {
            int es = t >> 4, kk = t & 15, hd = kk >> 2;
            int ds = dstS[es];
            if (ds >= 0) {
                float4 qd = *reinterpret_cast<const float4*>(g_qd + ds * 16 + hd * 4);
                const float2* kr = &kvs[es][hd * 4];
                float lg = kr[0].x * qd.x + kr[1].x * qd.y + kr[2].x * qd.z + kr[3].x * qd.w;
                float ex = expf(lg * LOGIT_SCALE * cutS[es]);
                if ((kk & 3) == 0) atomicAdd(&g_den[ds * 4 + hd], ex);
                atomicAdd(&g_agg[ds * 16 + kk], ex * kvs[es][kk].y);
            }
        }
        __syncthreads();
    }
}

// ---------------- finalize per node (W_out, skip, FFN) + re-zero --------------
__global__ void k_final(const float* __restrict__ xf,
                        const float* __restrict__ Wout,
                        const float* __restrict__ Wf1,
                        const float* __restrict__ Wf2,
                        float* __restrict__ out) {
    __shared__ float Wo[256], F1[512], F2[512];
    int t = threadIdx.x;
    if (t < 256) Wo[t] = Wout[t];
    for (int i = t; i < 512; i += 256) { F1[i] = Wf1[i]; F2[i] = Wf2[i]; }
    __syncthreads();
    int n = blockIdx.x * 256 + t;
    if (n >= NN) return;

    float a[16];
#pragma unroll
    for (int k = 0; k < 16; k++) {
        float d = g_den[n * 4 + (k >> 2)];
        a[k] = (d > 0.0f) ? g_agg[n * 16 + k] / d : 0.0f;
        g_agg[n * 16 + k] = 0.0f;            // re-zero for next replay
    }
#pragma unroll
    for (int h = 0; h < 4; h++) g_den[n * 4 + h] = 0.0f;
    float attn[16];
#pragma unroll
    for (int k = 0; k < 16; k++) {
        float s = xf[n * 16 + k];
#pragma unroll
        for (int jj = 0; jj < 16; jj++) s += a[jj] * Wo[jj * 16 + k];
        attn[k] = s;
    }
    float na[32];
#pragma unroll
    for (int jj = 0; jj < 32; jj++) {
        float f = 0.0f;
#pragma unroll
        for (int i = 0; i < 16; i++) f += attn[i] * F1[i * 32 + jj];
        na[jj] = f * sigmoidf_(fabsf(f));
    }
#pragma unroll
    for (int k = 0; k < 16; k++) {
        float o = attn[k];
#pragma unroll
        for (int jj = 0; jj < 32; jj++) o += na[jj] * F2[jj * 16 + k];
        out[n * 16 + k] = o;
    }
}

// ---------------- launch ------------------------------------------------------
extern "C" void kernel_launch(void* const* d_in, const int* in_sizes, int n_in,
                              void* d_out, int out_size) {
    const float* xf   = (const float*)d_in[0];
    const float* sh   = (const float*)d_in[1];
    const float* emb  = (const float*)d_in[2];
    const float* elen = (const float*)d_in[3];
    const float* Wq   = (const float*)d_in[4];
    const float* kW1  = (const float*)d_in[5];
    const float* kb1  = (const float*)d_in[6];
    const float* kW2  = (const float*)d_in[7];
    const float* kb2  = (const float*)d_in[8];
    const float* vW1  = (const float*)d_in[9];
    const float* vb1  = (const float*)d_in[10];
    const float* vW2  = (const float*)d_in[11];
    const float* vb2  = (const float*)d_in[12];
    const float* Wdot = (const float*)d_in[13];
    const float* Wout = (const float*)d_in[14];
    const float* Wf1  = (const float*)d_in[15];
    const float* Wf2  = (const float*)d_in[16];
    const int*   eidx = (const int*)d_in[17];
    float* out = (float*)d_out;

    k_pro1<<<PRO1_TOTAL, 256>>>(eidx, kW2, vW2, xf, Wq, Wdot, kb2, vb2,
                                sh, emb, elen, kW1, kb1, vW1, vb1);
    k_pro2<<<1257, 512>>>(xf);
    k_scatter<<<(EE + 255) / 256, 256>>>(eidx);
    k_edges<<<NN, 256>>>();
    k_final<<<(NN + 255) / 256, 256>>>(xf, Wout, Wf1, Wf2, out);
}

// round 13
// speedup vs baseline: 1.3095x; 1.0418x over previous
#include <cuda_runtime.h>
#include <cuda_fp16.h>
#include <math.h>

#define NN 10000
#define EE 100000
#define TP_NORM 0.125f       // 1/sqrt(C*S)
#define LOGIT_SCALE 0.125f   // DOT_NORM * SCALE
#define INV_RADIUS 0.2f

typedef unsigned long long u64;
typedef unsigned int u32;

// ---------------- scratch ----------------------------------------------------
__device__ u32  g_QhK[(size_t)NN * 2048];   // half2 pairs (hid 2h,2h+1): [n][(s*16+k)*32 + h]
__device__ u32  g_QhV[(size_t)NN * 2048];
__device__ u64  g_Qbkv[NN * 64];            // (K,V) f32 pairs: [n][s*16+k]
__device__ u64  g_WtK[32768];               // W2 transposed: [(c*64+sk)*32 + h]
__device__ u64  g_WtV[32768];
__device__ u32  g_h1K[(size_t)EE * 32];     // half2 pairs, ORIGINAL edge order
__device__ u32  g_h1V[(size_t)EE * 32];
__device__ float2 g_dc[EE];                 // (dst bitcast, cutoff), original order
__device__ float4 g_sh4[EE];                // sh, original order
__device__ float g_qd[NN * 16];             // q @ W_dot
__device__ int   g_deg[NN];
__device__ int   g_rowptr[NN + 1];
__device__ int   g_cursor[NN];
__device__ int   g_eorder[EE];
__device__ float g_den[NN * 4];
__device__ float g_agg[NN * 16];

__device__ __forceinline__ float sigmoidf_(float x) { return 1.0f / (1.0f + expf(-x)); }
__device__ __forceinline__ u64 pk2(float lo, float hi) {
    u64 r; asm("mov.b64 %0, {%1, %2};" : "=l"(r) : "f"(lo), "f"(hi)); return r;
}
__device__ __forceinline__ float2 up2(u64 v) {
    float2 f; asm("mov.b64 {%0, %1}, %2;" : "=f"(f.x), "=f"(f.y) : "l"(v)); return f;
}
__device__ __forceinline__ u64 dup2(float x) { return pk2(x, x); }
__device__ __forceinline__ u64 fma2_(u64 a, u64 b, u64 c) {
    u64 d; asm("fma.rn.f32x2 %0, %1, %2, %3;" : "=l"(d) : "l"(a), "l"(b), "l"(c)); return d;
}
__device__ __forceinline__ u32 pack_h2(float lo, float hi) {
    __half2 h = __floats2half2_rn(lo, hi);
    return *reinterpret_cast<u32*>(&h);
}
__device__ __forceinline__ __half2 as_h2(u32 v) { return *reinterpret_cast<__half2*>(&v); }
__device__ __forceinline__ u32 h2_as_u32(__half2 h) { return *reinterpret_cast<u32*>(&h); }

// silu on an f32 pair via tanh.approx.f16x2: silu(x) = (x/2)*(1+tanh(x/2))
__device__ __forceinline__ u32 silu_h2(float x0, float x1) {
    __half2 xh = __floats2half2_rn(x0, x1);
    __half2 m1 = __hmul2(xh, __float2half2_rn(0.5f));
    u32 thr; asm("tanh.approx.f16x2 %0, %1;" : "=r"(thr) : "r"(h2_as_u32(m1)));
    __half2 r = __hmul2(m1, __hadd2(as_h2(thr), __float2half2_rn(1.0f)));
    return h2_as_u32(r);
}

// ================= PRO1: fused independent prologue (256-thread blocks) ======
// block ranges: [0,391) hist | [391,647) transW | [647,1272) qprojd | [1272,4397) mlp(MMA)
#define PRO1_HIST   391
#define PRO1_TRANSW (PRO1_HIST + 256)
#define PRO1_QPROJD (PRO1_TRANSW + 625)
#define PRO1_TOTAL  (PRO1_QPROJD + 3125)

__global__ void __launch_bounds__(256) k_pro1(
    const int* __restrict__ eidx,
    const float* __restrict__ kW2, const float* __restrict__ vW2,
    const float* __restrict__ xf,  const float* __restrict__ Wq,
    const float* __restrict__ Wdot,
    const float* __restrict__ kb2, const float* __restrict__ vb2,
    const float* __restrict__ sh,  const float* __restrict__ emb,
    const float* __restrict__ elen,
    const float* __restrict__ kW1, const float* __restrict__ kb1,
    const float* __restrict__ vW1, const float* __restrict__ vb1) {

    int blk = blockIdx.x;
    int t = threadIdx.x;

    if (blk < PRO1_HIST) {
        int e = blk * 256 + t;
        if (e < EE) atomicAdd(&g_deg[eidx[e]], 1);

    } else if (blk < PRO1_TRANSW) {
        int b = blk - PRO1_HIST;
        int tz = b >> 7;
        int i = (b & 127) * 256 + t;
        const float* W = tz ? vW2 : kW2;
        u64* out = tz ? g_WtV : g_WtK;
        int h = i & 31, csk = i >> 5;
        out[i] = pk2(W[(2 * h) * 1024 + csk], W[(2 * h + 1) * 1024 + csk]);

    } else if (blk < PRO1_QPROJD) {
        __shared__ float Wqs[256], Wds[16], Xs[16][16], B2K[1024], B2V[1024];
        if (t < 256) Wqs[t] = Wq[t];
        if (t < 16)  Wds[t] = Wdot[t];
        for (int i = t; i < 1024; i += 256) { B2K[i] = kb2[i]; B2V[i] = vb2[i]; }
        int n0 = (blk - PRO1_TRANSW) * 16;
        { int nl = t >> 4, c = t & 15; Xs[nl][c] = xf[(n0 + nl) * 16 + c]; }
        __syncthreads();
        int nl = t >> 4, k = t & 15;
        int n = n0 + nl;
        int head = k >> 2, j = k & 3;
        float qd = 0.0f;
#pragma unroll
        for (int i2 = 0; i2 < 4; i2++) {
            float q = 0.0f;
#pragma unroll
            for (int c = 0; c < 16; c++) q += Xs[nl][c] * Wqs[c * 16 + head * 4 + i2];
            qd += q * Wds[i2 * 4 + j];
        }
        g_qd[n * 16 + k] = qd;
#pragma unroll
        for (int s = 0; s < 4; s++) {
            float aK = 0.0f, aV = 0.0f;
#pragma unroll
            for (int c = 0; c < 16; c++) {
                float x = Xs[nl][c];
                aK += x * B2K[c * 64 + s * 16 + k];
                aV += x * B2V[c * 64 + s * 16 + k];
            }
            g_Qbkv[n * 64 + s * 16 + k] = pk2(aK, aV);
        }

    } else {
        // ---- per-edge radial MLP via tensor cores: 32 edges per block ----
        __shared__ float W1s[16 * 128];     // combined [k][n]: n<64 = K, else V
        __shared__ float B1s[128];
        __shared__ u32   embh[32 * 8];      // emb as half2 pairs
        int e0 = (blk - PRO1_QPROJD) * 32;

        for (int i = t; i < 2048; i += 256) {
            int kk = i >> 7, n = i & 127;
            W1s[i] = (n < 64) ? kW1[kk * 64 + n] : vW1[kk * 64 + (n - 64)];
        }
        if (t < 128) B1s[t] = (t < 64) ? kb1[t] : vb1[t - 64];
        {
            int e = t >> 3, b2 = t & 7;
            float2 f2 = reinterpret_cast<const float2*>(emb)[(size_t)(e0 + e) * 8 + b2];
            embh[e * 8 + b2] = pack_h2(f2.x, f2.y);
        }
        if (t < 32) {
            int e = e0 + t;
            int ds = eidx[EE + e];
            float cut = sigmoidf_(10.0f * (1.0f - elen[e] * INV_RADIUS));
            g_dc[e] = make_float2(__int_as_float(ds), cut);
            g_sh4[e] = *reinterpret_cast<const float4*>(sh + e * 4);
        }
        __syncthreads();

        int lane = t & 31, w = t >> 5;
        int gq = lane >> 2, tid = lane & 3;
        int m = w >> 2;                 // M chunk (edge rows 16m..)
        int nq = w & 3;                 // 32-col group
        // A fragments (shared across the 4 n-chunks)
        u32 a0 = embh[(m * 16 + gq) * 8 + tid];
        u32 a1 = embh[(m * 16 + gq + 8) * 8 + tid];
        u32 a2 = embh[(m * 16 + gq) * 8 + tid + 4];
        u32 a3 = embh[(m * 16 + gq + 8) * 8 + tid + 4];

        u32* __restrict__ H = (nq < 2) ? g_h1K : g_h1V;
        int e_lo = e0 + m * 16 + gq;

#pragma unroll
        for (int j = 0; j < 4; j++) {
            int n0 = nq * 32 + j * 8;
            int n = n0 + gq;
            u32 b0 = pack_h2(W1s[(2 * tid) * 128 + n],     W1s[(2 * tid + 1) * 128 + n]);
            u32 b1 = pack_h2(W1s[(2 * tid + 8) * 128 + n], W1s[(2 * tid + 9) * 128 + n]);
            float c[4] = {0.f, 0.f, 0.f, 0.f};
            asm volatile(
                "mma.sync.aligned.m16n8k16.row.col.f32.f16.f16.f32 "
                "{%0,%1,%2,%3}, {%4,%5,%6,%7}, {%8,%9}, {%0,%1,%2,%3};"
                : "+f"(c[0]), "+f"(c[1]), "+f"(c[2]), "+f"(c[3])
                : "r"(a0), "r"(a1), "r"(a2), "r"(a3), "r"(b0), "r"(b1));
            float bb0 = B1s[n0 + 2 * tid], bb1 = B1s[n0 + 2 * tid + 1];
            int p = (nq & 1) * 16 + j * 4 + tid;   // pair index within K or V half
            H[(size_t)e_lo * 32 + p]       = silu_h2(c[0] + bb0, c[1] + bb1);
            H[(size_t)(e_lo + 8) * 32 + p] = silu_h2(c[2] + bb0, c[3] + bb1);
        }
    }
}

// ================= PRO2: scan (block 0) + qweights (blocks 1..1256) ==========
__global__ void __launch_bounds__(512) k_pro2(const float* __restrict__ xf) {
    int blk = blockIdx.x;
    int t = threadIdx.x;

    if (blk == 0) {
        __shared__ int ps[512];
        const int PER = 20;
        int start = t * PER;
        int sum = 0;
        int local[PER];
        for (int i = 0; i < PER; i++) {
            int idx = start + i;
            local[i] = (idx < NN) ? g_deg[idx] : 0;
            if (idx < NN) g_deg[idx] = 0;
            sum += local[i];
        }
        ps[t] = sum;
        __syncthreads();
        for (int off = 1; off < 512; off <<= 1) {
            int add = (t >= off) ? ps[t - off] : 0;
            __syncthreads();
            ps[t] += add;
            __syncthreads();
        }
        int base = ps[t] - sum;
        for (int i = 0; i < PER; i++) {
            int idx = start + i;
            if (idx < NN) { g_rowptr[idx] = base; g_cursor[idx] = base; base += local[i]; }
        }
        if (t == 511) g_rowptr[NN] = ps[511];

    } else {
        int b = blk - 1;
        int n0 = (b % 157) * 64;
        int h8 = ((b / 157) & 3) * 8;
        int tz = b / 628;
        __shared__ u64 Xd[64 * 16];
        for (int i = t; i < 1024; i += 512) {
            int n = n0 + (i >> 4);
            Xd[i] = dup2((n < NN) ? xf[n * 16 + (i & 15)] : 0.0f);
        }
        __syncthreads();
        int hp = t & 7, sk = t >> 3;
        const u64* __restrict__ Wt = tz ? g_WtV : g_WtK;
        u32* __restrict__ Qh = tz ? g_QhV : g_QhK;
        u64 wreg[16];
#pragma unroll
        for (int c = 0; c < 16; c++) wreg[c] = __ldg(&Wt[(c * 64 + sk) * 32 + h8 + hp]);
#pragma unroll 4
        for (int n = 0; n < 64; n++) {
            u64 acc = 0ULL;
#pragma unroll
            for (int c = 0; c < 16; c++) acc = fma2_(Xd[n * 16 + c], wreg[c], acc);
            if (n0 + n < NN) {
                float2 f = up2(acc);
                Qh[(size_t)(n0 + n) * 2048 + sk * 32 + h8 + hp] = pack_h2(f.x, f.y);
            }
        }
    }
}

// ---------------- scatter edges grouped by src --------------------------------
__global__ void k_scatter(const int* __restrict__ eidx) {
    int e = blockIdx.x * 256 + threadIdx.x;
    if (e < EE) {
        int s = eidx[e];
        int pos = atomicAdd(&g_cursor[s], 1);
        g_eorder[pos] = e;
    }
}

// ---------------- main edge contraction (one block per source node) -----------
// 256 threads: k = t>>4 (channel), g = t&15 (hid-pair slice, pair h = i*16+g).
// Q raw half2 regs; dd AND the 2-term hid-accumulate in HFMA2; f32 shfl reduce.
__global__ void __launch_bounds__(256, 4) k_edges() {
    __shared__ int    dstS[16];
    __shared__ float  cutS[16];
    __shared__ float4 shS[16];
    __shared__ u32    sh2S[16][4];      // duplicated-half2 sh per edge slot
    __shared__ u32    h1Ks[16][32];
    __shared__ u32    h1Vs[16][32];
    __shared__ float2 kvs[16][16];

    int node = blockIdx.x;
    int t = threadIdx.x;
    int k = t >> 4, g = t & 15;

    // per-node Q slice, kept packed as half2 (16+16 u32 registers)
    const u32* __restrict__ QK = g_QhK + (size_t)node * 2048;
    const u32* __restrict__ QV = g_QhV + (size_t)node * 2048;
    u32 qK[2][4], qV[2][4];
#pragma unroll
    for (int i = 0; i < 2; i++)
#pragma unroll
        for (int s = 0; s < 4; s++) {
            int idx = (s * 16 + k) * 32 + i * 16 + g;
            qK[i][s] = __ldg(&QK[idx]);
            qV[i][s] = __ldg(&QV[idx]);
        }

    int r0 = g_rowptr[node], deg = g_rowptr[node + 1] - r0;
    if (deg == 0) return;

    u64 qb[4];
    if (g == 0) {
#pragma unroll
        for (int s = 0; s < 4; s++) qb[s] = g_Qbkv[node * 64 + s * 16 + k];
    }

    for (int base = 0; base < deg; base += 16) {
        int nval = min(16, deg - base);
        // ---- staging: h1 tiles (2 rounds of 8 es) + per-edge meta ----
        {
            int esw = t >> 5, h = t & 31;
#pragma unroll
            for (int r = 0; r < 2; r++) {
                int es = r * 8 + esw;
                if (es < nval) {
                    int e = __ldg(&g_eorder[r0 + base + es]);
                    h1Ks[es][h] = __ldg(&g_h1K[(size_t)e * 32 + h]);
                    h1Vs[es][h] = __ldg(&g_h1V[(size_t)e * 32 + h]);
                }
            }
            if (t < 16) {
                if (t < nval) {
                    int e2 = __ldg(&g_eorder[r0 + base + t]);
                    float2 dc = g_dc[e2];
                    dstS[t] = __float_as_int(dc.x);
                    cutS[t] = dc.y;
                    float4 s4 = g_sh4[e2];
                    shS[t] = s4;
                    sh2S[t][0] = h2_as_u32(__float2half2_rn(s4.x));
                    sh2S[t][1] = h2_as_u32(__float2half2_rn(s4.y));
                    sh2S[t][2] = h2_as_u32(__float2half2_rn(s4.z));
                    sh2S[t][3] = h2_as_u32(__float2half2_rn(s4.w));
                } else {
                    dstS[t] = -1;
                }
            }
        }
        __syncthreads();

        // ---- compute: runtime-bounded loop over live edge slots ----
#pragma unroll 4
        for (int es = 0; es < nval; es++) {
            __half2 s0 = as_h2(sh2S[es][0]);
            __half2 s1 = as_h2(sh2S[es][1]);
            __half2 s2 = as_h2(sh2S[es][2]);
            __half2 s3 = as_h2(sh2S[es][3]);
            __half2 accK = __half2half2(__ushort_as_half(0));
            __half2 accV = accK;
#pragma unroll
            for (int i = 0; i < 2; i++) {
                __half2 dK = __hmul2(s0, as_h2(qK[i][0]));
                dK = __hfma2(s1, as_h2(qK[i][1]), dK);
                dK = __hfma2(s2, as_h2(qK[i][2]), dK);
                dK = __hfma2(s3, as_h2(qK[i][3]), dK);
                __half2 dV = __hmul2(s0, as_h2(qV[i][0]));
                dV = __hfma2(s1, as_h2(qV[i][1]), dV);
                dV = __hfma2(s2, as_h2(qV[i][2]), dV);
                dV = __hfma2(s3, as_h2(qV[i][3]), dV);
                accK = __hfma2(as_h2(h1Ks[es][i * 16 + g]), dK, accK);
                accV = __hfma2(as_h2(h1Vs[es][i * 16 + g]), dV, accV);
            }
            float2 fK = __half22float2(accK);
            float2 fV = __half22float2(accV);
            float kv_k = fK.x + fK.y;
            float kv_v = fV.x + fV.y;
            kv_k += __shfl_xor_sync(0xffffffffu, kv_k, 1);
            kv_v += __shfl_xor_sync(0xffffffffu, kv_v, 1);
            kv_k += __shfl_xor_sync(0xffffffffu, kv_k, 2);
            kv_v += __shfl_xor_sync(0xffffffffu, kv_v, 2);
            kv_k += __shfl_xor_sync(0xffffffffu, kv_k, 4);
            kv_v += __shfl_xor_sync(0xffffffffu, kv_v, 4);
            kv_k += __shfl_xor_sync(0xffffffffu, kv_k, 8);
            kv_v += __shfl_xor_sync(0xffffffffu, kv_v, 8);
            if (g == 0) {
                float4 s4 = shS[es];
                u64 bacc = fma2_(dup2(s4.x), qb[0], 0ULL);
                bacc = fma2_(dup2(s4.y), qb[1], bacc);
                bacc = fma2_(dup2(s4.z), qb[2], bacc);
                bacc = fma2_(dup2(s4.w), qb[3], bacc);
                float2 bb = up2(bacc);
                kvs[es][k] = make_float2((kv_k + bb.x) * TP_NORM, (kv_v + bb.y) * TP_NORM);
            }
        }
        __syncthreads();

        // ---- epilogue: all 256 threads, one atomic each (16 es x 16 kk) ----
        {
            int es = t >> 4, kk = t & 15, hd = kk >> 2;
            int ds = dstS[es];
            if (ds >= 0) {
                float4 qd = *reinterpret_cast<const float4*>(g_qd + ds * 16 + hd * 4);
                const float2* kr = &kvs[es][hd * 4];
                float lg = kr[0].x * qd.x + kr[1].x * qd.y + kr[2].x * qd.z + kr[3].x * qd.w;
                float ex = expf(lg * LOGIT_SCALE * cutS[es]);
                if ((kk & 3) == 0) atomicAdd(&g_den[ds * 4 + hd], ex);
                atomicAdd(&g_agg[ds * 16 + kk], ex * kvs[es][kk].y);
            }
        }
        __syncthreads();
    }
}

// ---------------- finalize per node (W_out, skip, FFN) + re-zero --------------
__global__ void k_final(const float* __restrict__ xf,
                        const float* __restrict__ Wout,
                        const float* __restrict__ Wf1,
                        const float* __restrict__ Wf2,
                        float* __restrict__ out) {
    __shared__ float Wo[256], F1[512], F2[512];
    int t = threadIdx.x;
    if (t < 256) Wo[t] = Wout[t];
    for (int i = t; i < 512; i += 256) { F1[i] = Wf1[i]; F2[i] = Wf2[i]; }
    __syncthreads();
    int n = blockIdx.x * 256 + t;
    if (n >= NN) return;

    float a[16];
#pragma unroll
    for (int k = 0; k < 16; k++) {
        float d = g_den[n * 4 + (k >> 2)];
        a[k] = (d > 0.0f) ? g_agg[n * 16 + k] / d : 0.0f;
        g_agg[n * 16 + k] = 0.0f;            // re-zero for next replay
    }
#pragma unroll
    for (int h = 0; h < 4; h++) g_den[n * 4 + h] = 0.0f;
    float attn[16];
#pragma unroll
    for (int k = 0; k < 16; k++) {
        float s = xf[n * 16 + k];
#pragma unroll
        for (int jj = 0; jj < 16; jj++) s += a[jj] * Wo[jj * 16 + k];
        attn[k] = s;
    }
    float na[32];
#pragma unroll
    for (int jj = 0; jj < 32; jj++) {
        float f = 0.0f;
#pragma unroll
        for (int i = 0; i < 16; i++) f += attn[i] * F1[i * 32 + jj];
        na[jj] = f * sigmoidf_(fabsf(f));
    }
#pragma unroll
    for (int k = 0; k < 16; k++) {
        float o = attn[k];
#pragma unroll
        for (int jj = 0; jj < 32; jj++) o += na[jj] * F2[jj * 16 + k];
        out[n * 16 + k] = o;
    }
}

// ---------------- launch ------------------------------------------------------
extern "C" void kernel_launch(void* const* d_in, const int* in_sizes, int n_in,
                              void* d_out, int out_size) {
    const float* xf   = (const float*)d_in[0];
    const float* sh   = (const float*)d_in[1];
    const float* emb  = (const float*)d_in[2];
    const float* elen = (const float*)d_in[3];
    const float* Wq   = (const float*)d_in[4];
    const float* kW1  = (const float*)d_in[5];
    const float* kb1  = (const float*)d_in[6];
    const float* kW2  = (const float*)d_in[7];
    const float* kb2  = (const float*)d_in[8];
    const float* vW1  = (const float*)d_in[9];
    const float* vb1  = (const float*)d_in[10];
    const float* vW2  = (const float*)d_in[11];
    const float* vb2  = (const float*)d_in[12];
    const float* Wdot = (const float*)d_in[13];
    const float* Wout = (const float*)d_in[14];
    const float* Wf1  = (const float*)d_in[15];
    const float* Wf2  = (const float*)d_in[16];
    const int*   eidx = (const int*)d_in[17];
    float* out = (float*)d_out;

    k_pro1<<<PRO1_TOTAL, 256>>>(eidx, kW2, vW2, xf, Wq, Wdot, kb2, vb2,
                                sh, emb, elen, kW1, kb1, vW1, vb1);
    k_pro2<<<1257, 512>>>(xf);
    k_scatter<<<(EE + 255) / 256, 256>>>(eidx);
    k_edges<<<NN, 256>>>();
    k_final<<<(NN + 255) / 256, 256>>>(xf, Wout, Wf1, Wf2, out);
}

// round 14
// speedup vs baseline: 1.4252x; 1.0883x over previous
#include <cuda_runtime.h>
#include <cuda_fp16.h>
#include <math.h>

#define NN 10000
#define EE 100000
#define TP_NORM 0.125f       // 1/sqrt(C*S)
#define LOGIT_SCALE 0.125f   // DOT_NORM * SCALE
#define INV_RADIUS 0.2f

typedef unsigned long long u64;
typedef unsigned int u32;

// ---------------- scratch ----------------------------------------------------
__device__ u32  g_QhK[(size_t)NN * 2048];   // half2 pairs (hid 2h,2h+1): [n][(s*16+k)*32 + h]
__device__ u32  g_QhV[(size_t)NN * 2048];
__device__ u64  g_Qbkv[NN * 64];            // (K,V) f32 pairs: [n][s*16+k]
__device__ u32  g_Wh[65536];                // fp16 B panel: [cp(8)][col(8192)], col = T*4096+sk*64+h
__device__ u32  g_h1K[(size_t)EE * 32];     // half2 pairs, ORIGINAL edge order
__device__ u32  g_h1V[(size_t)EE * 32];
__device__ float2 g_dc[EE];                 // (dst bitcast, cutoff), original order
__device__ float4 g_sh4[EE];                // sh, original order
__device__ float g_qd[NN * 16];             // q @ W_dot
__device__ int   g_deg[NN];
__device__ int   g_rowptr[NN + 1];
__device__ int   g_cursor[NN];
__device__ int   g_eorder[EE];
__device__ float g_den[NN * 4];
__device__ float g_agg[NN * 16];

__device__ __forceinline__ float sigmoidf_(float x) { return 1.0f / (1.0f + expf(-x)); }
__device__ __forceinline__ u64 pk2(float lo, float hi) {
    u64 r; asm("mov.b64 %0, {%1, %2};" : "=l"(r) : "f"(lo), "f"(hi)); return r;
}
__device__ __forceinline__ float2 up2(u64 v) {
    float2 f; asm("mov.b64 {%0, %1}, %2;" : "=f"(f.x), "=f"(f.y) : "l"(v)); return f;
}
__device__ __forceinline__ u64 dup2(float x) { return pk2(x, x); }
__device__ __forceinline__ u64 fma2_(u64 a, u64 b, u64 c) {
    u64 d; asm("fma.rn.f32x2 %0, %1, %2, %3;" : "=l"(d) : "l"(a), "l"(b), "l"(c)); return d;
}
__device__ __forceinline__ u32 pack_h2(float lo, float hi) {
    __half2 h = __floats2half2_rn(lo, hi);
    return *reinterpret_cast<u32*>(&h);
}
__device__ __forceinline__ __half2 as_h2(u32 v) { return *reinterpret_cast<__half2*>(&v); }
__device__ __forceinline__ u32 h2_as_u32(__half2 h) { return *reinterpret_cast<u32*>(&h); }

// silu on an f32 pair via tanh.approx.f16x2: silu(x) = (x/2)*(1+tanh(x/2))
__device__ __forceinline__ u32 silu_h2(float x0, float x1) {
    __half2 xh = __floats2half2_rn(x0, x1);
    __half2 m1 = __hmul2(xh, __float2half2_rn(0.5f));
    u32 thr; asm("tanh.approx.f16x2 %0, %1;" : "=r"(thr) : "r"(h2_as_u32(m1)));
    __half2 r = __hmul2(m1, __hadd2(as_h2(thr), __float2half2_rn(1.0f)));
    return h2_as_u32(r);
}

// ================= PRO1: fused independent prologue (256-thread blocks) ======
// block ranges: [0,391) hist | [391,647) transW | [647,1272) qprojd | [1272,4397) mlp(MMA)
#define PRO1_HIST   391
#define PRO1_TRANSW (PRO1_HIST + 256)
#define PRO1_QPROJD (PRO1_TRANSW + 625)
#define PRO1_TOTAL  (PRO1_QPROJD + 3125)

__global__ void __launch_bounds__(256) k_pro1(
    const int* __restrict__ eidx,
    const float* __restrict__ kW2, const float* __restrict__ vW2,
    const float* __restrict__ xf,  const float* __restrict__ Wq,
    const float* __restrict__ Wdot,
    const float* __restrict__ kb2, const float* __restrict__ vb2,
    const float* __restrict__ sh,  const float* __restrict__ emb,
    const float* __restrict__ elen,
    const float* __restrict__ kW1, const float* __restrict__ kb1,
    const float* __restrict__ vW1, const float* __restrict__ vb1) {

    int blk = blockIdx.x;
    int t = threadIdx.x;

    if (blk < PRO1_HIST) {
        int e = blk * 256 + t;
        if (e < EE) atomicAdd(&g_deg[eidx[e]], 1);

    } else if (blk < PRO1_TRANSW) {
        // ---- W2 -> fp16 B panel: g_Wh[cp*8192 + col], col = T*4096 + sk*64 + h
        int i = (blk - PRO1_HIST) * 256 + t;   // 0..65535
        int cp = i >> 13;                      // 0..7
        int col = i & 8191;
        int T = col >> 12;
        int sk = (col >> 6) & 63;
        int h = col & 63;
        const float* W = T ? vW2 : kW2;
        const float* base = W + h * 1024 + sk;
        g_Wh[i] = pack_h2(base[(2 * cp) * 64], base[(2 * cp + 1) * 64]);

    } else if (blk < PRO1_QPROJD) {
        __shared__ float Wqs[256], Wds[16], Xs[16][16], B2K[1024], B2V[1024];
        if (t < 256) Wqs[t] = Wq[t];
        if (t < 16)  Wds[t] = Wdot[t];
        for (int i = t; i < 1024; i += 256) { B2K[i] = kb2[i]; B2V[i] = vb2[i]; }
        int n0 = (blk - PRO1_TRANSW) * 16;
        { int nl = t >> 4, c = t & 15; Xs[nl][c] = xf[(n0 + nl) * 16 + c]; }
        __syncthreads();
        int nl = t >> 4, k = t & 15;
        int n = n0 + nl;
        int head = k >> 2, j = k & 3;
        float qd = 0.0f;
#pragma unroll
        for (int i2 = 0; i2 < 4; i2++) {
            float q = 0.0f;
#pragma unroll
            for (int c = 0; c < 16; c++) q += Xs[nl][c] * Wqs[c * 16 + head * 4 + i2];
            qd += q * Wds[i2 * 4 + j];
        }
        g_qd[n * 16 + k] = qd;
#pragma unroll
        for (int s = 0; s < 4; s++) {
            float aK = 0.0f, aV = 0.0f;
#pragma unroll
            for (int c = 0; c < 16; c++) {
                float x = Xs[nl][c];
                aK += x * B2K[c * 64 + s * 16 + k];
                aV += x * B2V[c * 64 + s * 16 + k];
            }
            g_Qbkv[n * 64 + s * 16 + k] = pk2(aK, aV);
        }

    } else {
        // ---- per-edge radial MLP via tensor cores: 32 edges per block ----
        __shared__ float W1s[16 * 128];     // combined [k][n]: n<64 = K, else V
        __shared__ float B1s[128];
        __shared__ u32   embh[32 * 8];      // emb as half2 pairs
        int e0 = (blk - PRO1_QPROJD) * 32;

        for (int i = t; i < 2048; i += 256) {
            int kk = i >> 7, n = i & 127;
            W1s[i] = (n < 64) ? kW1[kk * 64 + n] : vW1[kk * 64 + (n - 64)];
        }
        if (t < 128) B1s[t] = (t < 64) ? kb1[t] : vb1[t - 64];
        {
            int e = t >> 3, b2 = t & 7;
            float2 f2 = reinterpret_cast<const float2*>(emb)[(size_t)(e0 + e) * 8 + b2];
            embh[e * 8 + b2] = pack_h2(f2.x, f2.y);
        }
        if (t < 32) {
            int e = e0 + t;
            int ds = eidx[EE + e];
            float cut = sigmoidf_(10.0f * (1.0f - elen[e] * INV_RADIUS));
            g_dc[e] = make_float2(__int_as_float(ds), cut);
            g_sh4[e] = *reinterpret_cast<const float4*>(sh + e * 4);
        }
        __syncthreads();

        int lane = t & 31, w = t >> 5;
        int gq = lane >> 2, tid = lane & 3;
        int m = w >> 2;                 // M chunk (edge rows 16m..)
        int nq = w & 3;                 // 32-col group
        u32 a0 = embh[(m * 16 + gq) * 8 + tid];
        u32 a1 = embh[(m * 16 + gq + 8) * 8 + tid];
        u32 a2 = embh[(m * 16 + gq) * 8 + tid + 4];
        u32 a3 = embh[(m * 16 + gq + 8) * 8 + tid + 4];

        u32* __restrict__ H = (nq < 2) ? g_h1K : g_h1V;
        int e_lo = e0 + m * 16 + gq;

#pragma unroll
        for (int j = 0; j < 4; j++) {
            int n0 = nq * 32 + j * 8;
            int n = n0 + gq;
            u32 b0 = pack_h2(W1s[(2 * tid) * 128 + n],     W1s[(2 * tid + 1) * 128 + n]);
            u32 b1 = pack_h2(W1s[(2 * tid + 8) * 128 + n], W1s[(2 * tid + 9) * 128 + n]);
            float c[4] = {0.f, 0.f, 0.f, 0.f};
            asm volatile(
                "mma.sync.aligned.m16n8k16.row.col.f32.f16.f16.f32 "
                "{%0,%1,%2,%3}, {%4,%5,%6,%7}, {%8,%9}, {%0,%1,%2,%3};"
                : "+f"(c[0]), "+f"(c[1]), "+f"(c[2]), "+f"(c[3])
                : "r"(a0), "r"(a1), "r"(a2), "r"(a3), "r"(b0), "r"(b1));
            float bb0 = B1s[n0 + 2 * tid], bb1 = B1s[n0 + 2 * tid + 1];
            int p = (nq & 1) * 16 + j * 4 + tid;   // pair index within K or V half
            H[(size_t)e_lo * 32 + p]       = silu_h2(c[0] + bb0, c[1] + bb1);
            H[(size_t)(e_lo + 8) * 32 + p] = silu_h2(c[2] + bb0, c[3] + bb1);
        }
    }
}

// ================= PRO2: scan (block 0) + MMA qweights (blocks 1..2512) ======
__global__ void __launch_bounds__(512) k_pro2(const float* __restrict__ xf) {
    int blk = blockIdx.x;
    int t = threadIdx.x;

    if (blk == 0) {
        __shared__ int ps[512];
        const int PER = 20;
        int start = t * PER;
        int sum = 0;
        int local[PER];
        for (int i = 0; i < PER; i++) {
            int idx = start + i;
            local[i] = (idx < NN) ? g_deg[idx] : 0;
            if (idx < NN) g_deg[idx] = 0;
            sum += local[i];
        }
        ps[t] = sum;
        __syncthreads();
        for (int off = 1; off < 512; off <<= 1) {
            int add = (t >= off) ? ps[t - off] : 0;
            __syncthreads();
            ps[t] += add;
            __syncthreads();
        }
        int base = ps[t] - sum;
        for (int i = 0; i < PER; i++) {
            int idx = start + i;
            if (idx < NN) { g_rowptr[idx] = base; g_cursor[idx] = base; base += local[i]; }
        }
        if (t == 511) g_rowptr[NN] = ps[511];

    } else {
        // ---- Q tensors via tensor cores: 64 nodes x 512 cols per block ----
        __shared__ u32 Xh[512];             // [node(64)][cp(8)] fp16 pairs
        __shared__ u32 Bs[8 * 520];         // [cp][col], 520-padded
        int b = blk - 1;                    // 0..2511
        int n0 = (b % 157) * 64;
        int col0 = (b / 157) * 512;         // 0..7680

        {
            int n = t >> 3, cp = t & 7;
            int nn = n0 + n;
            float x0 = (nn < NN) ? xf[nn * 16 + 2 * cp] : 0.0f;
            float x1 = (nn < NN) ? xf[nn * 16 + 2 * cp + 1] : 0.0f;
            Xh[t] = pack_h2(x0, x1);
        }
#pragma unroll
        for (int j = 0; j < 8; j++) {
            int i = t + j * 512;
            int cp = i >> 9, cl = i & 511;
            Bs[cp * 520 + cl] = __ldg(&g_Wh[cp * 8192 + col0 + cl]);
        }
        __syncthreads();

        int lane = t & 31, w = t >> 5;
        int gq = lane >> 2, tid = lane & 3;
        int m = w & 3;                      // node 16-row chunk
        int nc0 = w >> 2;                   // n-chunk group (0..3)
        int r0 = m * 16 + gq;
        u32 a0 = Xh[r0 * 8 + tid];
        u32 a1 = Xh[(r0 + 8) * 8 + tid];
        u32 a2 = Xh[r0 * 8 + tid + 4];
        u32 a3 = Xh[(r0 + 8) * 8 + tid + 4];
        int na = n0 + r0, nb = na + 8;
        int gbase = (col0 >> 1);            // global colpair base

#pragma unroll
        for (int j = 0; j < 16; j++) {
            int nc = nc0 * 16 + j;          // 0..63
            int cl = nc * 8 + gq;
            u32 b0 = Bs[tid * 520 + cl];
            u32 b1 = Bs[(tid + 4) * 520 + cl];
            float c[4] = {0.f, 0.f, 0.f, 0.f};
            asm volatile(
                "mma.sync.aligned.m16n8k16.row.col.f32.f16.f16.f32 "
                "{%0,%1,%2,%3}, {%4,%5,%6,%7}, {%8,%9}, {%0,%1,%2,%3};"
                : "+f"(c[0]), "+f"(c[1]), "+f"(c[2]), "+f"(c[3])
                : "r"(a0), "r"(a1), "r"(a2), "r"(a3), "r"(b0), "r"(b1));
            int g = gbase + nc * 4 + tid;   // global colpair 0..4095
            u32* __restrict__ Q = (g < 2048) ? g_QhK : g_QhV;
            int idx = g & 2047;
            if (na < NN) Q[(size_t)na * 2048 + idx] = pack_h2(c[0], c[1]);
            if (nb < NN) Q[(size_t)nb * 2048 + idx] = pack_h2(c[2], c[3]);
        }
    }
}

// ---------------- scatter edges grouped by src --------------------------------
__global__ void k_scatter(const int* __restrict__ eidx) {
    int e = blockIdx.x * 256 + threadIdx.x;
    if (e < EE) {
        int s = eidx[e];
        int pos = atomicAdd(&g_cursor[s], 1);
        g_eorder[pos] = e;
    }
}

// ---------------- main edge contraction (one block per source node) -----------
// 256 threads: k = t>>4 (channel), g = t&15 (hid-pair slice, pair h = i*16+g).
// Q raw half2 regs; dd AND the 2-term hid-accumulate in HFMA2; f32 shfl reduce.
__global__ void __launch_bounds__(256, 4) k_edges() {
    __shared__ int    dstS[16];
    __shared__ float  cutS[16];
    __shared__ float4 shS[16];
    __shared__ u32    sh2S[16][4];      // duplicated-half2 sh per edge slot
    __shared__ u32    h1Ks[16][32];
    __shared__ u32    h1Vs[16][32];
    __shared__ float2 kvs[16][16];

    int node = blockIdx.x;
    int t = threadIdx.x;
    int k = t >> 4, g = t & 15;

    // per-node Q slice, kept packed as half2 (16+16 u32 registers)
    const u32* __restrict__ QK = g_QhK + (size_t)node * 2048;
    const u32* __restrict__ QV = g_QhV + (size_t)node * 2048;
    u32 qK[2][4], qV[2][4];
#pragma unroll
    for (int i = 0; i < 2; i++)
#pragma unroll
        for (int s = 0; s < 4; s++) {
            int idx = (s * 16 + k) * 32 + i * 16 + g;
            qK[i][s] = __ldg(&QK[idx]);
            qV[i][s] = __ldg(&QV[idx]);
        }

    int r0 = g_rowptr[node], deg = g_rowptr[node + 1] - r0;
    if (deg == 0) return;

    u64 qb[4];
    if (g == 0) {
#pragma unroll
        for (int s = 0; s < 4; s++) qb[s] = g_Qbkv[node * 64 + s * 16 + k];
    }

    for (int base = 0; base < deg; base += 16) {
        int nval = min(16, deg - base);
        // ---- staging: h1 tiles (2 rounds of 8 es) + per-edge meta ----
        {
            int esw = t >> 5, h = t & 31;
#pragma unroll
            for (int r = 0; r < 2; r++) {
                int es = r * 8 + esw;
                if (es < nval) {
                    int e = __ldg(&g_eorder[r0 + base + es]);
                    h1Ks[es][h] = __ldg(&g_h1K[(size_t)e * 32 + h]);
                    h1Vs[es][h] = __ldg(&g_h1V[(size_t)e * 32 + h]);
                }
            }
            if (t < 16) {
                if (t < nval) {
                    int e2 = __ldg(&g_eorder[r0 + base + t]);
                    float2 dc = g_dc[e2];
                    dstS[t] = __float_as_int(dc.x);
                    cutS[t] = dc.y;
                    float4 s4 = g_sh4[e2];
                    shS[t] = s4;
                    sh2S[t][0] = h2_as_u32(__float2half2_rn(s4.x));
                    sh2S[t][1] = h2_as_u32(__float2half2_rn(s4.y));
                    sh2S[t][2] = h2_as_u32(__float2half2_rn(s4.z));
                    sh2S[t][3] = h2_as_u32(__float2half2_rn(s4.w));
                } else {
                    dstS[t] = -1;
                }
            }
        }
        __syncthreads();

        // ---- compute: runtime-bounded loop over live edge slots ----
#pragma unroll 4
        for (int es = 0; es < nval; es++) {
            __half2 s0 = as_h2(sh2S[es][0]);
            __half2 s1 = as_h2(sh2S[es][1]);
            __half2 s2 = as_h2(sh2S[es][2]);
            __half2 s3 = as_h2(sh2S[es][3]);
            __half2 accK = __half2half2(__ushort_as_half(0));
            __half2 accV = accK;
#pragma unroll
            for (int i = 0; i < 2; i++) {
                __half2 dK = __hmul2(s0, as_h2(qK[i][0]));
                dK = __hfma2(s1, as_h2(qK[i][1]), dK);
                dK = __hfma2(s2, as_h2(qK[i][2]), dK);
                dK = __hfma2(s3, as_h2(qK[i][3]), dK);
                __half2 dV = __hmul2(s0, as_h2(qV[i][0]));
                dV = __hfma2(s1, as_h2(qV[i][1]), dV);
                dV = __hfma2(s2, as_h2(qV[i][2]), dV);
                dV = __hfma2(s3, as_h2(qV[i][3]), dV);
                accK = __hfma2(as_h2(h1Ks[es][i * 16 + g]), dK, accK);
                accV = __hfma2(as_h2(h1Vs[es][i * 16 + g]), dV, accV);
            }
            float2 fK = __half22float2(accK);
            float2 fV = __half22float2(accV);
            float kv_k = fK.x + fK.y;
            float kv_v = fV.x + fV.y;
            kv_k += __shfl_xor_sync(0xffffffffu, kv_k, 1);
            kv_v += __shfl_xor_sync(0xffffffffu, kv_v, 1);
            kv_k += __shfl_xor_sync(0xffffffffu, kv_k, 2);
            kv_v += __shfl_xor_sync(0xffffffffu, kv_v, 2);
            kv_k += __shfl_xor_sync(0xffffffffu, kv_k, 4);
            kv_v += __shfl_xor_sync(0xffffffffu, kv_v, 4);
            kv_k += __shfl_xor_sync(0xffffffffu, kv_k, 8);
            kv_v += __shfl_xor_sync(0xffffffffu, kv_v, 8);
            if (g == 0) {
                float4 s4 = shS[es];
                u64 bacc = fma2_(dup2(s4.x), qb[0], 0ULL);
                bacc = fma2_(dup2(s4.y), qb[1], bacc);
                bacc = fma2_(dup2(s4.z), qb[2], bacc);
                bacc = fma2_(dup2(s4.w), qb[3], bacc);
                float2 bb = up2(bacc);
                kvs[es][k] = make_float2((kv_k + bb.x) * TP_NORM, (kv_v + bb.y) * TP_NORM);
            }
        }
        __syncthreads();

        // ---- epilogue: all 256 threads, one atomic each (16 es x 16 kk) ----
        {
            int es = t >> 4, kk = t & 15, hd = kk >> 2;
            int ds = dstS[es];
            if (ds >= 0) {
                float4 qd = *reinterpret_cast<const float4*>(g_qd + ds * 16 + hd * 4);
                const float2* kr = &kvs[es][hd * 4];
                float lg = kr[0].x * qd.x + kr[1].x * qd.y + kr[2].x * qd.z + kr[3].x * qd.w;
                float ex = expf(lg * LOGIT_SCALE * cutS[es]);
                if ((kk & 3) == 0) atomicAdd(&g_den[ds * 4 + hd], ex);
                atomicAdd(&g_agg[ds * 16 + kk], ex * kvs[es][kk].y);
            }
        }
        __syncthreads();
    }
}

// ---------------- finalize per node (W_out, skip, FFN) + re-zero --------------
__global__ void k_final(const float* __restrict__ xf,
                        const float* __restrict__ Wout,
                        const float* __restrict__ Wf1,
                        const float* __restrict__ Wf2,
                        float* __restrict__ out) {
    __shared__ float Wo[256], F1[512], F2[512];
    int t = threadIdx.x;
    if (t < 256) Wo[t] = Wout[t];
    for (int i = t; i < 512; i += 256) { F1[i] = Wf1[i]; F2[i] = Wf2[i]; }
    __syncthreads();
    int n = blockIdx.x * 256 + t;
    if (n >= NN) return;

    float a[16];
#pragma unroll
    for (int k = 0; k < 16; k++) {
        float d = g_den[n * 4 + (k >> 2)];
        a[k] = (d > 0.0f) ? g_agg[n * 16 + k] / d : 0.0f;
        g_agg[n * 16 + k] = 0.0f;            // re-zero for next replay
    }
#pragma unroll
    for (int h = 0; h < 4; h++) g_den[n * 4 + h] = 0.0f;
    float attn[16];
#pragma unroll
    for (int k = 0; k < 16; k++) {
        float s = xf[n * 16 + k];
#pragma unroll
        for (int jj = 0; jj < 16; jj++) s += a[jj] * Wo[jj * 16 + k];
        attn[k] = s;
    }
    float na[32];
#pragma unroll
    for (int jj = 0; jj < 32; jj++) {
        float f = 0.0f;
#pragma unroll
        for (int i = 0; i < 16; i++) f += attn[i] * F1[i * 32 + jj];
        na[jj] = f * sigmoidf_(fabsf(f));
    }
#pragma unroll
    for (int k = 0; k < 16; k++) {
        float o = attn[k];
#pragma unroll
        for (int jj = 0; jj < 32; jj++) o += na[jj] * F2[jj * 16 + k];
        out[n * 16 + k] = o;
    }
}

// ---------------- launch ------------------------------------------------------
extern "C" void kernel_launch(void* const* d_in, const int* in_sizes, int n_in,
                              void* d_out, int out_size) {
    const float* xf   = (const float*)d_in[0];
    const float* sh   = (const float*)d_in[1];
    const float* emb  = (const float*)d_in[2];
    const float* elen = (const float*)d_in[3];
    const float* Wq   = (const float*)d_in[4];
    const float* kW1  = (const float*)d_in[5];
    const float* kb1  = (const float*)d_in[6];
    const float* kW2  = (const float*)d_in[7];
    const float* kb2  = (const float*)d_in[8];
    const float* vW1  = (const float*)d_in[9];
    const float* vb1  = (const float*)d_in[10];
    const float* vW2  = (const float*)d_in[11];
    const float* vb2  = (const float*)d_in[12];
    const float* Wdot = (const float*)d_in[13];
    const float* Wout = (const float*)d_in[14];
    const float* Wf1  = (const float*)d_in[15];
    const float* Wf2  = (const float*)d_in[16];
    const int*   eidx = (const int*)d_in[17];
    float* out = (float*)d_out;

    k_pro1<<<PRO1_TOTAL, 256>>>(eidx, kW2, vW2, xf, Wq, Wdot, kb2, vb2,
                                sh, emb, elen, kW1, kb1, vW1, vb1);
    k_pro2<<<2513, 512>>>(xf);
    k_scatter<<<(EE + 255) / 256, 256>>>(eidx);
    k_edges<<<NN, 256>>>();
    k_final<<<(NN + 255) / 256, 256>>>(xf, Wout, Wf1, Wf2, out);
}

// round 16
// speedup vs baseline: 1.5601x; 1.0947x over previous
#include <cuda_runtime.h>
#include <cuda_fp16.h>
#include <math.h>

#define NN 10000
#define EE 100000
#define TP_NORM 0.125f       // 1/sqrt(C*S)
#define LOGIT_SCALE 0.125f   // DOT_NORM * SCALE
#define INV_RADIUS 0.2f

typedef unsigned long long u64;
typedef unsigned int u32;

// ---------------- scratch ----------------------------------------------------
__device__ u32  g_QhK[(size_t)NN * 2048];   // half2 pairs (hid 2h,2h+1): [n][(s*16+k)*32 + h]
__device__ u32  g_QhV[(size_t)NN * 2048];
__device__ u64  g_Qbkv[NN * 64];            // (K,V) f32 pairs: [n][s*16+k]
__device__ u32  g_Wh[65536];                // fp16 B panel: [cp(8)][col(8192)], col = T*4096+sk*64+h
__device__ u32  g_h1K[(size_t)EE * 32];     // half2 pairs, ORIGINAL edge order
__device__ u32  g_h1V[(size_t)EE * 32];
__device__ float2 g_dc[EE];                 // (dst bitcast, cutoff), original order
__device__ float4 g_sh4[EE];                // sh, original order
__device__ float g_qd[NN * 16];             // q @ W_dot
__device__ int   g_deg[NN];
__device__ int   g_rowptr[NN + 1];
__device__ int   g_cursor[NN];
__device__ int   g_eorder[EE];
__device__ float g_den[NN * 4];
__device__ float g_agg[NN * 16];

__device__ __forceinline__ float sigmoidf_(float x) { return 1.0f / (1.0f + expf(-x)); }
__device__ __forceinline__ u64 pk2(float lo, float hi) {
    u64 r; asm("mov.b64 %0, {%1, %2};" : "=l"(r) : "f"(lo), "f"(hi)); return r;
}
__device__ __forceinline__ float2 up2(u64 v) {
    float2 f; asm("mov.b64 {%0, %1}, %2;" : "=f"(f.x), "=f"(f.y) : "l"(v)); return f;
}
__device__ __forceinline__ u64 dup2(float x) { return pk2(x, x); }
__device__ __forceinline__ u64 fma2_(u64 a, u64 b, u64 c) {
    u64 d; asm("fma.rn.f32x2 %0, %1, %2, %3;" : "=l"(d) : "l"(a), "l"(b), "l"(c)); return d;
}
__device__ __forceinline__ u32 pack_h2(float lo, float hi) {
    __half2 h = __floats2half2_rn(lo, hi);
    return *reinterpret_cast<u32*>(&h);
}
__device__ __forceinline__ __half2 as_h2(u32 v) { return *reinterpret_cast<__half2*>(&v); }
__device__ __forceinline__ u32 h2_as_u32(__half2 h) { return *reinterpret_cast<u32*>(&h); }

// silu on an f32 pair via tanh.approx.f16x2: silu(x) = (x/2)*(1+tanh(x/2))
__device__ __forceinline__ u32 silu_h2(float x0, float x1) {
    __half2 xh = __floats2half2_rn(x0, x1);
    __half2 m1 = __hmul2(xh, __float2half2_rn(0.5f));
    u32 thr; asm("tanh.approx.f16x2 %0, %1;" : "=r"(thr) : "r"(h2_as_u32(m1)));
    __half2 r = __hmul2(m1, __hadd2(as_h2(thr), __float2half2_rn(1.0f)));
    return h2_as_u32(r);
}

// ================= PRO1: fused independent prologue (256-thread blocks) ======
// block ranges: [0,391) hist | [391,647) transW | [647,1272) qprojd | [1272,2054) mlp(MMA,128/blk)
#define PRO1_HIST   391
#define PRO1_TRANSW (PRO1_HIST + 256)
#define PRO1_QPROJD (PRO1_TRANSW + 625)
#define PRO1_TOTAL  (PRO1_QPROJD + 782)

__global__ void __launch_bounds__(256) k_pro1(
    const int* __restrict__ eidx,
    const float* __restrict__ kW2, const float* __restrict__ vW2,
    const float* __restrict__ xf,  const float* __restrict__ Wq,
    const float* __restrict__ Wdot,
    const float* __restrict__ kb2, const float* __restrict__ vb2,
    const float* __restrict__ sh,  const float* __restrict__ emb,
    const float* __restrict__ elen,
    const float* __restrict__ kW1, const float* __restrict__ kb1,
    const float* __restrict__ vW1, const float* __restrict__ vb1) {

    int blk = blockIdx.x;
    int t = threadIdx.x;

    if (blk < PRO1_HIST) {
        int e = blk * 256 + t;
        if (e < EE) atomicAdd(&g_deg[eidx[e]], 1);

    } else if (blk < PRO1_TRANSW) {
        // ---- W2 -> fp16 B panel: g_Wh[cp*8192 + col], col = T*4096 + sk*64 + h
        int i = (blk - PRO1_HIST) * 256 + t;   // 0..65535
        int cp = i >> 13;                      // 0..7
        int col = i & 8191;
        int T = col >> 12;
        int sk = (col >> 6) & 63;
        int h = col & 63;
        const float* W = T ? vW2 : kW2;
        const float* base = W + h * 1024 + sk;
        g_Wh[i] = pack_h2(base[(2 * cp) * 64], base[(2 * cp + 1) * 64]);

    } else if (blk < PRO1_QPROJD) {
        __shared__ float Wqs[256], Wds[16], Xs[16][16], B2K[1024], B2V[1024];
        if (t < 256) Wqs[t] = Wq[t];
        if (t < 16)  Wds[t] = Wdot[t];
        for (int i = t; i < 1024; i += 256) { B2K[i] = kb2[i]; B2V[i] = vb2[i]; }
        int n0 = (blk - PRO1_TRANSW) * 16;
        { int nl = t >> 4, c = t & 15; Xs[nl][c] = xf[(n0 + nl) * 16 + c]; }
        __syncthreads();
        int nl = t >> 4, k = t & 15;
        int n = n0 + nl;
        int head = k >> 2, j = k & 3;
        float qd = 0.0f;
#pragma unroll
        for (int i2 = 0; i2 < 4; i2++) {
            float q = 0.0f;
#pragma unroll
            for (int c = 0; c < 16; c++) q += Xs[nl][c] * Wqs[c * 16 + head * 4 + i2];
            qd += q * Wds[i2 * 4 + j];
        }
        g_qd[n * 16 + k] = qd;
#pragma unroll
        for (int s = 0; s < 4; s++) {
            float aK = 0.0f, aV = 0.0f;
#pragma unroll
            for (int c = 0; c < 16; c++) {
                float x = Xs[nl][c];
                aK += x * B2K[c * 64 + s * 16 + k];
                aV += x * B2V[c * 64 + s * 16 + k];
            }
            g_Qbkv[n * 64 + s * 16 + k] = pk2(aK, aV);
        }

    } else {
        // ---- per-edge radial MLP via tensor cores: 128 edges per block ----
        __shared__ float W1s[16 * 128];     // combined [k][n]: n<64 = K, else V
        __shared__ float B1s[128];
        __shared__ u32   embh[128 * 8];     // emb as half2 pairs
        int e0 = (blk - PRO1_QPROJD) * 128;

        for (int i = t; i < 2048; i += 256) {
            int kk = i >> 7, n = i & 127;
            W1s[i] = (n < 64) ? kW1[kk * 64 + n] : vW1[kk * 64 + (n - 64)];
        }
        if (t < 128) B1s[t] = (t < 64) ? kb1[t] : vb1[t - 64];
        for (int i = t; i < 1024; i += 256) {
            int e = i >> 3, b2 = i & 7;
            int ee = e0 + e;
            if (ee < EE) {
                float2 f2 = reinterpret_cast<const float2*>(emb)[(size_t)ee * 8 + b2];
                embh[i] = pack_h2(f2.x, f2.y);
            } else embh[i] = 0u;
        }
        if (t < 128) {
            int e = e0 + t;
            if (e < EE) {
                int ds = eidx[EE + e];
                float cut = sigmoidf_(10.0f * (1.0f - elen[e] * INV_RADIUS));
                g_dc[e] = make_float2(__int_as_float(ds), cut);
                g_sh4[e] = *reinterpret_cast<const float4*>(sh + e * 4);
            }
        }
        __syncthreads();

        int lane = t & 31, w = t >> 5;
        int gq = lane >> 2, tid = lane & 3;
        int m = w >> 2;                 // 16-row chunk within 32-edge sub-tile
        int nq = w & 3;                 // 32-col group
        u32* __restrict__ H = (nq < 2) ? g_h1K : g_h1V;

#pragma unroll
        for (int m2 = 0; m2 < 4; m2++) {
            int row = m2 * 32 + m * 16;
            u32 a0 = embh[(row + gq) * 8 + tid];
            u32 a1 = embh[(row + gq + 8) * 8 + tid];
            u32 a2 = embh[(row + gq) * 8 + tid + 4];
            u32 a3 = embh[(row + gq + 8) * 8 + tid + 4];
            int e_lo = e0 + row + gq;
#pragma unroll
            for (int j = 0; j < 4; j++) {
                int n0 = nq * 32 + j * 8;
                int n = n0 + gq;
                u32 b0 = pack_h2(W1s[(2 * tid) * 128 + n],     W1s[(2 * tid + 1) * 128 + n]);
                u32 b1 = pack_h2(W1s[(2 * tid + 8) * 128 + n], W1s[(2 * tid + 9) * 128 + n]);
                float c[4] = {0.f, 0.f, 0.f, 0.f};
                asm volatile(
                    "mma.sync.aligned.m16n8k16.row.col.f32.f16.f16.f32 "
                    "{%0,%1,%2,%3}, {%4,%5,%6,%7}, {%8,%9}, {%0,%1,%2,%3};"
                    : "+f"(c[0]), "+f"(c[1]), "+f"(c[2]), "+f"(c[3])
                    : "r"(a0), "r"(a1), "r"(a2), "r"(a3), "r"(b0), "r"(b1));
                float bb0 = B1s[n0 + 2 * tid], bb1 = B1s[n0 + 2 * tid + 1];
                int p = (nq & 1) * 16 + j * 4 + tid;
                if (e_lo < EE)     H[(size_t)e_lo * 32 + p]       = silu_h2(c[0] + bb0, c[1] + bb1);
                if (e_lo + 8 < EE) H[(size_t)(e_lo + 8) * 32 + p] = silu_h2(c[2] + bb0, c[3] + bb1);
            }
        }
    }
}

// ====== PRO2: scan (block 0) + MMA qweights 128 nodes x 512 cols (1..1264) ===
__global__ void __launch_bounds__(512) k_pro2(const float* __restrict__ xf) {
    int blk = blockIdx.x;
    int t = threadIdx.x;

    if (blk == 0) {
        __shared__ int ps[512];
        const int PER = 20;
        int start = t * PER;
        int sum = 0;
        int local[PER];
        for (int i = 0; i < PER; i++) {
            int idx = start + i;
            local[i] = (idx < NN) ? g_deg[idx] : 0;
            if (idx < NN) g_deg[idx] = 0;
            sum += local[i];
        }
        ps[t] = sum;
        __syncthreads();
        for (int off = 1; off < 512; off <<= 1) {
            int add = (t >= off) ? ps[t - off] : 0;
            __syncthreads();
            ps[t] += add;
            __syncthreads();
        }
        int base = ps[t] - sum;
        for (int i = 0; i < PER; i++) {
            int idx = start + i;
            if (idx < NN) { g_rowptr[idx] = base; g_cursor[idx] = base; base += local[i]; }
        }
        if (t == 511) g_rowptr[NN] = ps[511];

    } else {
        // ---- Q tensors via tensor cores: 128 nodes x 512 cols per block ----
        __shared__ u32 Xh[1024];            // [node(128)][cp(8)] fp16 pairs
        __shared__ u32 Bs[8 * 520];         // [cp][col], 520-padded
        int b = blk - 1;                    // 0..1263
        int nt = b % 79, ct = b / 79;       // 79 node-tiles x 16 col-tiles
        int n0 = nt * 128;
        int col0 = ct * 512;                // 0..7680

        for (int i = t; i < 1024; i += 512) {
            int n = i >> 3, cp = i & 7;
            int nn = n0 + n;
            float x0 = (nn < NN) ? xf[nn * 16 + 2 * cp] : 0.0f;
            float x1 = (nn < NN) ? xf[nn * 16 + 2 * cp + 1] : 0.0f;
            Xh[i] = pack_h2(x0, x1);
        }
#pragma unroll
        for (int j = 0; j < 8; j++) {
            int i = t + j * 512;
            int cp = i >> 9, cl = i & 511;
            Bs[cp * 520 + cl] = __ldg(&g_Wh[cp * 8192 + col0 + cl]);
        }
        __syncthreads();

        int lane = t & 31, w = t >> 5;
        int gq = lane >> 2, tid = lane & 3;
        int m = w & 3;                      // node 16-row chunk
        int nc0 = w >> 2;                   // n-chunk group (0..3)
        int gbase = (col0 >> 1);            // global colpair base

#pragma unroll
        for (int sub = 0; sub < 2; sub++) {
            int r0 = sub * 64 + m * 16 + gq;
            u32 a0 = Xh[r0 * 8 + tid];
            u32 a1 = Xh[(r0 + 8) * 8 + tid];
            u32 a2 = Xh[r0 * 8 + tid + 4];
            u32 a3 = Xh[(r0 + 8) * 8 + tid + 4];
            int na = n0 + r0, nb = na + 8;
#pragma unroll
            for (int j = 0; j < 16; j++) {
                int nc = nc0 * 16 + j;          // 0..63
                int cl = nc * 8 + gq;
                u32 b0 = Bs[tid * 520 + cl];
                u32 b1 = Bs[(tid + 4) * 520 + cl];
                float c[4] = {0.f, 0.f, 0.f, 0.f};
                asm volatile(
                    "mma.sync.aligned.m16n8k16.row.col.f32.f16.f16.f32 "
                    "{%0,%1,%2,%3}, {%4,%5,%6,%7}, {%8,%9}, {%0,%1,%2,%3};"
                    : "+f"(c[0]), "+f"(c[1]), "+f"(c[2]), "+f"(c[3])
                    : "r"(a0), "r"(a1), "r"(a2), "r"(a3), "r"(b0), "r"(b1));
                int g = gbase + nc * 4 + tid;   // global colpair 0..4095
                u32* __restrict__ Q = (g < 2048) ? g_QhK : g_QhV;
                int idx = g & 2047;
                if (na < NN) Q[(size_t)na * 2048 + idx] = pack_h2(c[0], c[1]);
                if (nb < NN) Q[(size_t)nb * 2048 + idx] = pack_h2(c[2], c[3]);
            }
        }
    }
}

// ---------------- scatter edges grouped by src --------------------------------
__global__ void k_scatter(const int* __restrict__ eidx) {
    int e = blockIdx.x * 256 + threadIdx.x;
    if (e < EE) {
        int s = eidx[e];
        int pos = atomicAdd(&g_cursor[s], 1);
        g_eorder[pos] = e;
    }
}

// ---------------- main edge contraction (one block per source node) -----------
// 256 threads: k = t>>4 (channel), g = t&15 (hid-pair slice, pair h = i*16+g).
// Q raw half2 regs; dd AND the 2-term hid-accumulate in HFMA2; f32 shfl reduce.
__global__ void __launch_bounds__(256, 4) k_edges() {
    __shared__ int    dstS[16];
    __shared__ float  cutS[16];
    __shared__ float4 shS[16];
    __shared__ u32    sh2S[16][4];      // duplicated-half2 sh per edge slot
    __shared__ u32    h1Ks[16][32];
    __shared__ u32    h1Vs[16][32];
    __shared__ float2 kvs[16][16];

    int node = blockIdx.x;
    int t = threadIdx.x;
    int k = t >> 4, g = t & 15;

    // per-node Q slice, kept packed as half2 (16+16 u32 registers)
    const u32* __restrict__ QK = g_QhK + (size_t)node * 2048;
    const u32* __restrict__ QV = g_QhV + (size_t)node * 2048;
    u32 qK[2][4], qV[2][4];
#pragma unroll
    for (int i = 0; i < 2; i++)
#pragma unroll
        for (int s = 0; s < 4; s++) {
            int idx = (s * 16 + k) * 32 + i * 16 + g;
            qK[i][s] = __ldg(&QK[idx]);
            qV[i][s] = __ldg(&QV[idx]);
        }

    int r0 = g_rowptr[node], deg = g_rowptr[node + 1] - r0;
    if (deg == 0) return;

    u64 qb[4];
    if (g == 0) {
#pragma unroll
        for (int s = 0; s < 4; s++) qb[s] = g_Qbkv[node * 64 + s * 16 + k];
    }

    for (int base = 0; base < deg; base += 16) {
        int nval = min(16, deg - base);
        // ---- staging: h1 tiles (2 rounds of 8 es) + per-edge meta ----
        {
            int esw = t >> 5, h = t & 31;
#pragma unroll
            for (int r = 0; r < 2; r++) {
                int es = r * 8 + esw;
                if (es < nval) {
                    int e = __ldg(&g_eorder[r0 + base + es]);
                    h1Ks[es][h] = __ldg(&g_h1K[(size_t)e * 32 + h]);
                    h1Vs[es][h] = __ldg(&g_h1V[(size_t)e * 32 + h]);
                }
            }
            if (t < 16) {
                if (t < nval) {
                    int e2 = __ldg(&g_eorder[r0 + base + t]);
                    float2 dc = g_dc[e2];
                    dstS[t] = __float_as_int(dc.x);
                    cutS[t] = dc.y;
                    float4 s4 = g_sh4[e2];
                    shS[t] = s4;
                    sh2S[t][0] = h2_as_u32(__float2half2_rn(s4.x));
                    sh2S[t][1] = h2_as_u32(__float2half2_rn(s4.y));
                    sh2S[t][2] = h2_as_u32(__float2half2_rn(s4.z));
                    sh2S[t][3] = h2_as_u32(__float2half2_rn(s4.w));
                } else {
                    dstS[t] = -1;
                }
            }
        }
        __syncthreads();

        // ---- compute: runtime-bounded loop over live edge slots ----
#pragma unroll 4
        for (int es = 0; es < nval; es++) {
            __half2 s0 = as_h2(sh2S[es][0]);
            __half2 s1 = as_h2(sh2S[es][1]);
            __half2 s2 = as_h2(sh2S[es][2]);
            __half2 s3 = as_h2(sh2S[es][3]);
            __half2 accK = __half2half2(__ushort_as_half(0));
            __half2 accV = accK;
#pragma unroll
            for (int i = 0; i < 2; i++) {
                __half2 dK = __hmul2(s0, as_h2(qK[i][0]));
                dK = __hfma2(s1, as_h2(qK[i][1]), dK);
                dK = __hfma2(s2, as_h2(qK[i][2]), dK);
                dK = __hfma2(s3, as_h2(qK[i][3]), dK);
                __half2 dV = __hmul2(s0, as_h2(qV[i][0]));
                dV = __hfma2(s1, as_h2(qV[i][1]), dV);
                dV = __hfma2(s2, as_h2(qV[i][2]), dV);
                dV = __hfma2(s3, as_h2(qV[i][3]), dV);
                accK = __hfma2(as_h2(h1Ks[es][i * 16 + g]), dK, accK);
                accV = __hfma2(as_h2(h1Vs[es][i * 16 + g]), dV, accV);
            }
            float2 fK = __half22float2(accK);
            float2 fV = __half22float2(accV);
            float kv_k = fK.x + fK.y;
            float kv_v = fV.x + fV.y;
            kv_k += __shfl_xor_sync(0xffffffffu, kv_k, 1);
            kv_v += __shfl_xor_sync(0xffffffffu, kv_v, 1);
            kv_k += __shfl_xor_sync(0xffffffffu, kv_k, 2);
            kv_v += __shfl_xor_sync(0xffffffffu, kv_v, 2);
            kv_k += __shfl_xor_sync(0xffffffffu, kv_k, 4);
            kv_v += __shfl_xor_sync(0xffffffffu, kv_v, 4);
            kv_k += __shfl_xor_sync(0xffffffffu, kv_k, 8);
            kv_v += __shfl_xor_sync(0xffffffffu, kv_v, 8);
            if (g == 0) {
                float4 s4 = shS[es];
                u64 bacc = fma2_(dup2(s4.x), qb[0], 0ULL);
                bacc = fma2_(dup2(s4.y), qb[1], bacc);
                bacc = fma2_(dup2(s4.z), qb[2], bacc);
                bacc = fma2_(dup2(s4.w), qb[3], bacc);
                float2 bb = up2(bacc);
                kvs[es][k] = make_float2((kv_k + bb.x) * TP_NORM, (kv_v + bb.y) * TP_NORM);
            }
        }
        __syncthreads();

        // ---- epilogue: all 256 threads, one atomic each (16 es x 16 kk) ----
        {
            int es = t >> 4, kk = t & 15, hd = kk >> 2;
            int ds = dstS[es];
            if (ds >= 0) {
                float4 qd = *reinterpret_cast<const float4*>(g_qd + ds * 16 + hd * 4);
                const float2* kr = &kvs[es][hd * 4];
                float lg = kr[0].x * qd.x + kr[1].x * qd.y + kr[2].x * qd.z + kr[3].x * qd.w;
                float ex = expf(lg * LOGIT_SCALE * cutS[es]);
                if ((kk & 3) == 0) atomicAdd(&g_den[ds * 4 + hd], ex);
                atomicAdd(&g_agg[ds * 16 + kk], ex * kvs[es][kk].y);
            }
        }
        __syncthreads();
    }
}

// ---------------- finalize per node (W_out, skip, FFN) + re-zero --------------
__global__ void k_final(const float* __restrict__ xf,
                        const float* __restrict__ Wout,
                        const float* __restrict__ Wf1,
                        const float* __restrict__ Wf2,
                        float* __restrict__ out) {
    __shared__ float Wo[256], F1[512], F2[512];
    int t = threadIdx.x;
    if (t < 256) Wo[t] = Wout[t];
    for (int i = t; i < 512; i += 256) { F1[i] = Wf1[i]; F2[i] = Wf2[i]; }
    __syncthreads();
    int n = blockIdx.x * 256 + t;
    if (n >= NN) return;

    float a[16];
#pragma unroll
    for (int k = 0; k < 16; k++) {
        float d = g_den[n * 4 + (k >> 2)];
        a[k] = (d > 0.0f) ? g_agg[n * 16 + k] / d : 0.0f;
        g_agg[n * 16 + k] = 0.0f;            // re-zero for next replay
    }
#pragma unroll
    for (int h = 0; h < 4; h++) g_den[n * 4 + h] = 0.0f;
    float attn[16];
#pragma unroll
    for (int k = 0; k < 16; k++) {
        float s = xf[n * 16 + k];
#pragma unroll
        for (int jj = 0; jj < 16; jj++) s += a[jj] * Wo[jj * 16 + k];
        attn[k] = s;
    }
    float na[32];
#pragma unroll
    for (int jj = 0; jj < 32; jj++) {
        float f = 0.0f;
#pragma unroll
        for (int i = 0; i < 16; i++) f += attn[i] * F1[i * 32 + jj];
        na[jj] = f * sigmoidf_(fabsf(f));
    }
#pragma unroll
    for (int k = 0; k < 16; k++) {
        float o = attn[k];
#pragma unroll
        for (int jj = 0; jj < 32; jj++) o += na[jj] * F2[jj * 16 + k];
        out[n * 16 + k] = o;
    }
}

// ---------------- launch ------------------------------------------------------
extern "C" void kernel_launch(void* const* d_in, const int* in_sizes, int n_in,
                              void* d_out, int out_size) {
    const float* xf   = (const float*)d_in[0];
    const float* sh   = (const float*)d_in[1];
    const float* emb  = (const float*)d_in[2];
    const float* elen = (const float*)d_in[3];
    const float* Wq   = (const float*)d_in[4];
    const float* kW1  = (const float*)d_in[5];
    const float* kb1  = (const float*)d_in[6];
    const float* kW2  = (const float*)d_in[7];
    const float* kb2  = (const float*)d_in[8];
    const float* vW1  = (const float*)d_in[9];
    const float* vb1  = (const float*)d_in[10];
    const float* vW2  = (const float*)d_in[11];
    const float* vb2  = (const float*)d_in[12];
    const float* Wdot = (const float*)d_in[13];
    const float* Wout = (const float*)d_in[14];
    const float* Wf1  = (const float*)d_in[15];
    const float* Wf2  = (const float*)d_in[16];
    const int*   eidx = (const int*)d_in[17];
    float* out = (float*)d_out;

    k_pro1<<<PRO1_TOTAL, 256>>>(eidx, kW2, vW2, xf, Wq, Wdot, kb2, vb2,
                                sh, emb, elen, kW1, kb1, vW1, vb1);
    k_pro2<<<1265, 512>>>(xf);
    k_scatter<<<(EE + 255) / 256, 256>>>(eidx);
    k_edges<<<NN, 256>>>();
    k_final<<<(NN + 255) / 256, 256>>>(xf, Wout, Wf1, Wf2, out);
}